// round 3
// baseline (speedup 1.0000x reference)
#include <cuda_runtime.h>
#include <cstdint>

#define S_LEN 4096
#define HID   1024
#define NH    16
#define HD    64
#define WIN   512
#define HALF  256
#define QT    32      // queries per attention block
#define KC    128     // key chunk
#define NCHUNK 5      // covers [q0-256, q0+384) >= needed [q0-256, q0+287]

// ---- scratch (no cudaMalloc allowed); referenced only from device code ----
__device__ float g_q[S_LEN * HID];
__device__ float g_k[S_LEN * HID];
__device__ float g_v[S_LEN * HID];
__device__ float g_ctx[S_LEN * HID];

// buffer tags: 0 = external pointer, 1..4 = device scratch
__device__ __forceinline__ float* buf_ptr(int tag, float* ext) {
    switch (tag) {
        case 1: return g_q;
        case 2: return g_k;
        case 3: return g_v;
        case 4: return g_ctx;
        default: return ext;
    }
}
__device__ __forceinline__ const float* cbuf_ptr(int tag, const float* ext) {
    switch (tag) {
        case 1: return g_q;
        case 2: return g_k;
        case 3: return g_v;
        case 4: return g_ctx;
        default: return ext;
    }
}

// ============================================================================
// fp32 GEMM: C[M,N] = A[M,K] @ B[K,N] + bias[N]
// BM=BN=128, BK=8, 256 threads, 8x8 per thread
// A and C can be external pointers or device-scratch (selected by tag).
// ============================================================================
__global__ __launch_bounds__(256)
void sgemm_bias(const float* __restrict__ Aext, int Atag,
                const float* __restrict__ B,
                const float* __restrict__ bias,
                float* __restrict__ Cext, int Ctag,
                int M, int N, int K)
{
    __shared__ float As[8][128];
    __shared__ float Bs[8][128];

    const float* A = cbuf_ptr(Atag, Aext);
    float*       C = buf_ptr(Ctag, Cext);

    const int tid = threadIdx.x;
    const int m0 = blockIdx.y * 128;
    const int n0 = blockIdx.x * 128;
    const int tr = tid >> 4;          // 0..15
    const int tc = tid & 15;          // 0..15

    const int aRow = tid >> 1;              // 0..127
    const int aCol = (tid & 1) << 2;        // 0 or 4
    const int bRow = tid >> 5;              // 0..7
    const int bCol = (tid & 31) << 2;       // 0..124

    float acc[8][8];
#pragma unroll
    for (int i = 0; i < 8; i++)
#pragma unroll
        for (int j = 0; j < 8; j++) acc[i][j] = 0.f;

    const float* Ap = A + (size_t)(m0 + aRow) * K + aCol;
    const float* Bp = B + (size_t)bRow * N + n0 + bCol;

    for (int k0 = 0; k0 < K; k0 += 8) {
        float4 a = *(const float4*)(Ap + k0);
        As[aCol + 0][aRow] = a.x;
        As[aCol + 1][aRow] = a.y;
        As[aCol + 2][aRow] = a.z;
        As[aCol + 3][aRow] = a.w;
        float4 b = *(const float4*)(Bp + (size_t)k0 * N);
        *(float4*)&Bs[bRow][bCol] = b;
        __syncthreads();

#pragma unroll
        for (int k = 0; k < 8; k++) {
            float rm[8], rn[8];
            *(float4*)&rm[0] = *(const float4*)&As[k][tr * 8];
            *(float4*)&rm[4] = *(const float4*)&As[k][tr * 8 + 4];
            *(float4*)&rn[0] = *(const float4*)&Bs[k][tc * 8];
            *(float4*)&rn[4] = *(const float4*)&Bs[k][tc * 8 + 4];
#pragma unroll
            for (int i = 0; i < 8; i++)
#pragma unroll
                for (int j = 0; j < 8; j++)
                    acc[i][j] = fmaf(rm[i], rn[j], acc[i][j]);
        }
        __syncthreads();
    }

    float bv[8];
#pragma unroll
    for (int j = 0; j < 8; j++) bv[j] = bias[n0 + tc * 8 + j];

#pragma unroll
    for (int i = 0; i < 8; i++) {
        float* cp = C + (size_t)(m0 + tr * 8 + i) * N + n0 + tc * 8;
        float4 o0 = make_float4(acc[i][0] + bv[0], acc[i][1] + bv[1],
                                acc[i][2] + bv[2], acc[i][3] + bv[3]);
        float4 o1 = make_float4(acc[i][4] + bv[4], acc[i][5] + bv[5],
                                acc[i][6] + bv[6], acc[i][7] + bv[7]);
        *(float4*)cp = o0;
        *(float4*)(cp + 4) = o1;
    }
}

// ============================================================================
// Sliding-window attention. Block = (head, query tile of 32).
// Zero-padded semantics: OOB keys score exactly 0 and ARE in the softmax.
// Dynamic smem layout (floats):
//   S  [32][512]  score band           16384
//   KV            K^T (64x132) / V (128x68) union  8704
//   Qs [32][68]                        2176
// ============================================================================
#define SMEM_FLOATS (QT * WIN + 8704 + QT * 68)

__global__ __launch_bounds__(256)
void attn_kernel(float* __restrict__ probs, int write_probs)
{
    extern __shared__ float sm[];
    float* S  = sm;                    // QT*WIN
    float* KV = sm + QT * WIN;         // 8704
    float* Qs = KV + 8704;             // QT*68

    const int t    = threadIdx.x;
    const int q0   = blockIdx.x * QT;
    const int h    = blockIdx.y;
    const int hoff = h * HD;

    // ---- load Q tile ----
#pragma unroll
    for (int r = 0; r < (QT * HD) / 256; r++) {
        int idx = r * 256 + t;
        int qi = idx >> 6, d = idx & 63;
        Qs[qi * 68 + d] = g_q[(size_t)(q0 + qi) * HID + hoff + d];
    }

    // ---- scores: thread = (2 queries) x (8 keys) ----
    const int qp  = t >> 4;        // 0..15
    const int jg  = t & 15;        // 0..15
    const int qa  = qp * 2, qb = qa + 1;
    const int jj0 = jg * 8;

    for (int c = 0; c < NCHUNK; c++) {
        const int kb = q0 - HALF + c * KC;
        __syncthreads();   // also covers Q-load on first iteration
        // load K chunk transposed: KV[d*132 + j], zero for OOB keys
#pragma unroll
        for (int r = 0; r < (KC * HD) / 256; r++) {
            int idx = r * 256 + t;
            int j = idx >> 6, d = idx & 63;
            int key = kb + j;
            KV[d * 132 + j] = (key >= 0 && key < S_LEN)
                ? g_k[(size_t)key * HID + hoff + d] : 0.f;
        }
        __syncthreads();

        float accA[8], accB[8];
#pragma unroll
        for (int e = 0; e < 8; e++) { accA[e] = 0.f; accB[e] = 0.f; }

#pragma unroll 4
        for (int d = 0; d < HD; d++) {
            float qva = Qs[qa * 68 + d];
            float qvb = Qs[qb * 68 + d];
            const float4* kr = (const float4*)&KV[d * 132 + jj0];
            float4 k0 = kr[0], k1 = kr[1];
            accA[0] = fmaf(qva, k0.x, accA[0]);
            accA[1] = fmaf(qva, k0.y, accA[1]);
            accA[2] = fmaf(qva, k0.z, accA[2]);
            accA[3] = fmaf(qva, k0.w, accA[3]);
            accA[4] = fmaf(qva, k1.x, accA[4]);
            accA[5] = fmaf(qva, k1.y, accA[5]);
            accA[6] = fmaf(qva, k1.z, accA[6]);
            accA[7] = fmaf(qva, k1.w, accA[7]);
            accB[0] = fmaf(qvb, k0.x, accB[0]);
            accB[1] = fmaf(qvb, k0.y, accB[1]);
            accB[2] = fmaf(qvb, k0.z, accB[2]);
            accB[3] = fmaf(qvb, k0.w, accB[3]);
            accB[4] = fmaf(qvb, k1.x, accB[4]);
            accB[5] = fmaf(qvb, k1.y, accB[5]);
            accB[6] = fmaf(qvb, k1.z, accB[6]);
            accB[7] = fmaf(qvb, k1.w, accB[7]);
        }

        // scatter into the W-wide band (w = key - i + HALF), scale by 1/sqrt(64)
#pragma unroll
        for (int e = 0; e < 8; e++) {
            int key = kb + jj0 + e;
            int wA = key - (q0 + qa) + HALF;
            if ((unsigned)wA < WIN) S[qa * WIN + wA] = accA[e] * 0.125f;
            int wB = key - (q0 + qb) + HALF;
            if ((unsigned)wB < WIN) S[qb * WIN + wB] = accB[e] * 0.125f;
        }
    }
    __syncthreads();

    // ---- softmax over 512 (zeros for padded keys INCLUDED) + probs write ----
    const int wid = t >> 5, lane = t & 31;
#pragma unroll
    for (int qi = 0; qi < 4; qi++) {
        int qq = wid * 4 + qi;
        float* Sr = &S[qq * WIN];
        float m = -3.4e38f;
        for (int w = lane; w < WIN; w += 32) m = fmaxf(m, Sr[w]);
#pragma unroll
        for (int o = 16; o; o >>= 1) m = fmaxf(m, __shfl_xor_sync(0xFFFFFFFFu, m, o));
        float ssum = 0.f;
        for (int w = lane; w < WIN; w += 32) {
            float e = expf(Sr[w] - m);
            Sr[w] = e;
            ssum += e;
        }
#pragma unroll
        for (int o = 16; o; o >>= 1) ssum += __shfl_xor_sync(0xFFFFFFFFu, ssum, o);
        float inv = 1.f / ssum;
        if (write_probs) {
            float* pr = &probs[((size_t)h * S_LEN + q0 + qq) * WIN];
            for (int w = lane; w < WIN; w += 32) {
                float p = Sr[w] * inv;
                Sr[w] = p;
                pr[w] = p;
            }
        } else {
            for (int w = lane; w < WIN; w += 32) Sr[w] *= inv;
        }
    }

    // ---- ctx = P @ V : thread = (1 query) x (8 dims) ----
    const int cq = t >> 3;        // 0..31
    const int d0 = (t & 7) * 8;   // 0..56
    float acc[8];
#pragma unroll
    for (int e = 0; e < 8; e++) acc[e] = 0.f;

    for (int c = 0; c < NCHUNK; c++) {
        const int kb = q0 - HALF + c * KC;
        __syncthreads();
        // load V chunk row-major: KV[j*68 + d], zero for OOB keys
#pragma unroll
        for (int r = 0; r < (KC * HD) / 256; r++) {
            int idx = r * 256 + t;
            int j = idx >> 6, d = idx & 63;
            int key = kb + j;
            KV[j * 68 + d] = (key >= 0 && key < S_LEN)
                ? g_v[(size_t)key * HID + hoff + d] : 0.f;
        }
        __syncthreads();

        const int wbase = kb - (q0 + cq) + HALF;
        int jlo = wbase < 0 ? -wbase : 0;
        int jhi = (WIN - wbase) < KC ? (WIN - wbase) : KC;
        if (jhi < 0) jhi = 0;
        for (int j = jlo; j < jhi; j++) {
            float p = S[cq * WIN + wbase + j];
            const float4* vr = (const float4*)&KV[j * 68 + d0];
            float4 v0 = vr[0], v1 = vr[1];
            acc[0] = fmaf(p, v0.x, acc[0]);
            acc[1] = fmaf(p, v0.y, acc[1]);
            acc[2] = fmaf(p, v0.z, acc[2]);
            acc[3] = fmaf(p, v0.w, acc[3]);
            acc[4] = fmaf(p, v1.x, acc[4]);
            acc[5] = fmaf(p, v1.y, acc[5]);
            acc[6] = fmaf(p, v1.z, acc[6]);
            acc[7] = fmaf(p, v1.w, acc[7]);
        }
    }

    float* cp = &g_ctx[(size_t)(q0 + cq) * HID + hoff + d0];
    *(float4*)cp       = make_float4(acc[0], acc[1], acc[2], acc[3]);
    *(float4*)(cp + 4) = make_float4(acc[4], acc[5], acc[6], acc[7]);
}

// ============================================================================
extern "C" void kernel_launch(void* const* d_in, const int* in_sizes, int n_in,
                              void* d_out, int out_size)
{
    const float* X  = (const float*)d_in[0];  // [1,4096,1024]
    const float* Wq = (const float*)d_in[1];
    const float* bq = (const float*)d_in[2];
    const float* Wk = (const float*)d_in[3];
    const float* bk = (const float*)d_in[4];
    const float* Wv = (const float*)d_in[5];
    const float* bv = (const float*)d_in[6];
    const float* Wo = (const float*)d_in[7];
    const float* bo = (const float*)d_in[8];

    float* out = (float*)d_out;
    const size_t OUT_ELEMS   = (size_t)S_LEN * HID;         // 4194304
    const size_t PROBS_ELEMS = (size_t)NH * S_LEN * WIN;    // 33554432
    float* probs = out + OUT_ELEMS;
    int write_probs = ((size_t)out_size >= OUT_ELEMS + PROBS_ELEMS) ? 1 : 0;

    // idempotent, deterministic, non-stream API (safe under graph capture)
    cudaFuncSetAttribute(attn_kernel,
                         cudaFuncAttributeMaxDynamicSharedMemorySize,
                         SMEM_FLOATS * (int)sizeof(float));

    dim3 ggrid(HID / 128, S_LEN / 128);   // (8, 32)
    // X @ Wq -> g_q (tag 1), X @ Wk -> g_k (tag 2), X @ Wv -> g_v (tag 3)
    sgemm_bias<<<ggrid, 256>>>(X, 0, Wq, bq, nullptr, 1, S_LEN, HID, HID);
    sgemm_bias<<<ggrid, 256>>>(X, 0, Wk, bk, nullptr, 2, S_LEN, HID, HID);
    sgemm_bias<<<ggrid, 256>>>(X, 0, Wv, bv, nullptr, 3, S_LEN, HID, HID);

    dim3 agrid(S_LEN / QT, NH);           // (128, 16)
    attn_kernel<<<agrid, 256, SMEM_FLOATS * sizeof(float)>>>(probs, write_probs);

    // g_ctx (tag 4) @ Wo -> out
    sgemm_bias<<<ggrid, 256>>>(nullptr, 4, Wo, bo, out, 0, S_LEN, HID, HID);
}

// round 4
// speedup vs baseline: 1.2804x; 1.2804x over previous
#include <cuda_runtime.h>
#include <cstdint>

#define S_LEN 4096
#define HID   1024
#define NH    16
#define HD    64
#define WIN   512
#define HALF  256
#define QT    32      // queries per attention block
#define COV   544     // key coverage per block: [q0-256, q0+287]
#define SST   548     // S row stride (floats)
#define KST   268     // K^T row stride (floats, mult of 4, conflict-friendly)
#define VST   68      // V row stride (floats)

// ---- scratch (no cudaMalloc allowed); referenced only from device code ----
__device__ float g_q[S_LEN * HID];
__device__ float g_k[S_LEN * HID];
__device__ float g_v[S_LEN * HID];
__device__ float g_ctx[S_LEN * HID];

// buffer tags: 0 = external pointer, 1..4 = device scratch
__device__ __forceinline__ float* buf_ptr(int tag, float* ext) {
    switch (tag) {
        case 1: return g_q;
        case 2: return g_k;
        case 3: return g_v;
        case 4: return g_ctx;
        default: return ext;
    }
}
__device__ __forceinline__ const float* cbuf_ptr(int tag, const float* ext) {
    switch (tag) {
        case 1: return g_q;
        case 2: return g_k;
        case 3: return g_v;
        case 4: return g_ctx;
        default: return ext;
    }
}

// ============================================================================
// fp32 GEMM: C[M,N] = A[M,K] @ B[K,N] + bias[N]   (unchanged from round 3)
// ============================================================================
__global__ __launch_bounds__(256)
void sgemm_bias(const float* __restrict__ Aext, int Atag,
                const float* __restrict__ B,
                const float* __restrict__ bias,
                float* __restrict__ Cext, int Ctag,
                int M, int N, int K)
{
    __shared__ float As[8][128];
    __shared__ float Bs[8][128];

    const float* A = cbuf_ptr(Atag, Aext);
    float*       C = buf_ptr(Ctag, Cext);

    const int tid = threadIdx.x;
    const int m0 = blockIdx.y * 128;
    const int n0 = blockIdx.x * 128;
    const int tr = tid >> 4;
    const int tc = tid & 15;

    const int aRow = tid >> 1;
    const int aCol = (tid & 1) << 2;
    const int bRow = tid >> 5;
    const int bCol = (tid & 31) << 2;

    float acc[8][8];
#pragma unroll
    for (int i = 0; i < 8; i++)
#pragma unroll
        for (int j = 0; j < 8; j++) acc[i][j] = 0.f;

    const float* Ap = A + (size_t)(m0 + aRow) * K + aCol;
    const float* Bp = B + (size_t)bRow * N + n0 + bCol;

    for (int k0 = 0; k0 < K; k0 += 8) {
        float4 a = *(const float4*)(Ap + k0);
        As[aCol + 0][aRow] = a.x;
        As[aCol + 1][aRow] = a.y;
        As[aCol + 2][aRow] = a.z;
        As[aCol + 3][aRow] = a.w;
        float4 b = *(const float4*)(Bp + (size_t)k0 * N);
        *(float4*)&Bs[bRow][bCol] = b;
        __syncthreads();

#pragma unroll
        for (int k = 0; k < 8; k++) {
            float rm[8], rn[8];
            *(float4*)&rm[0] = *(const float4*)&As[k][tr * 8];
            *(float4*)&rm[4] = *(const float4*)&As[k][tr * 8 + 4];
            *(float4*)&rn[0] = *(const float4*)&Bs[k][tc * 8];
            *(float4*)&rn[4] = *(const float4*)&Bs[k][tc * 8 + 4];
#pragma unroll
            for (int i = 0; i < 8; i++)
#pragma unroll
                for (int j = 0; j < 8; j++)
                    acc[i][j] = fmaf(rm[i], rn[j], acc[i][j]);
        }
        __syncthreads();
    }

    float bv[8];
#pragma unroll
    for (int j = 0; j < 8; j++) bv[j] = bias[n0 + tc * 8 + j];

#pragma unroll
    for (int i = 0; i < 8; i++) {
        float* cp = C + (size_t)(m0 + tr * 8 + i) * N + n0 + tc * 8;
        float4 o0 = make_float4(acc[i][0] + bv[0], acc[i][1] + bv[1],
                                acc[i][2] + bv[2], acc[i][3] + bv[3]);
        float4 o1 = make_float4(acc[i][4] + bv[4], acc[i][5] + bv[5],
                                acc[i][6] + bv[6], acc[i][7] + bv[7]);
        *(float4*)cp = o0;
        *(float4*)(cp + 4) = o1;
    }
}

// ============================================================================
// Sliding-window attention, absolute-column layout.
// S[qi][c], c = key - kmin, kmin = q0-256, c in [0,544). Band: w = c - qi in [0,512).
// exp without max-subtraction (|score| <= ~18, fp32-safe; softmax shift-invariant).
// Invalid band entries stored as 0 so PV and row-sum are uniform dense loops.
// smem (floats): S 32x548 =17536 | KV 64x268=17152 (V reuses: 128x68) |
//                Qs 32x68 = 2176 | sinv 32  -> total 36896 floats = 147,584 B
// ============================================================================
#define SM_S   0
#define SM_KV  17536
#define SM_Q   34688
#define SM_INV 36864
#define SMEM_FLOATS 36896

__global__ __launch_bounds__(256)
void attn_kernel(float* __restrict__ probs, int write_probs)
{
    extern __shared__ float sm[];
    float* S    = sm + SM_S;
    float* KV   = sm + SM_KV;
    float* Qs   = sm + SM_Q;
    float* sinv = sm + SM_INV;

    const int t    = threadIdx.x;
    const int lane = t & 31;
    const int wv   = t >> 5;           // warp id 0..7
    const int q0   = blockIdx.x * QT;
    const int h    = blockIdx.y;
    const int hoff = h * HD;
    const int kmin = q0 - HALF;

    // ---- load Q tile: 32x64 floats as float4 ----
#pragma unroll
    for (int r = 0; r < 2; r++) {
        int f4 = r * 256 + t;          // 0..511
        int qi = f4 >> 4;
        int d4 = (f4 & 15) << 2;
        *(float4*)&Qs[qi * VST + d4] =
            *(const float4*)&g_q[(size_t)(q0 + qi) * HID + hoff + d4];
    }

    // ======================= QK phase =======================
    // chunks of 256,256,32 keys. Thread tile: 4 queries x 8 keys.
    const int qg  = wv;                // warp owns 4 queries (qg*4..+3)
    const int jg  = lane;              // 8 keys at jg*8
    const int lkk = lane >> 2;         // loader: key-within-octet
    const int ld4 = (lane & 3) << 2;   // loader: d4 base

    for (int cc = 0; cc < 3; cc++) {
        const int cb = cc << 8;
        const int W  = (cc == 2) ? 32 : 256;
        __syncthreads();
        // load K^T chunk: KV[d][j], zero OOB keys
        for (int kg = 0; kg < 4; kg++) {
            int jloc = kg * 64 + wv * 8 + lkk;
            if (jloc >= W) break;
            int key = kmin + cb + jloc;
            const bool ok = (key >= 0 && key < S_LEN);
            const float* src = &g_k[(size_t)key * HID + hoff];
#pragma unroll
            for (int dq = 0; dq < 4; dq++) {
                int d4 = dq * 16 + ld4;
                float4 kv = ok ? *(const float4*)(src + d4)
                               : make_float4(0.f, 0.f, 0.f, 0.f);
                KV[(d4 + 0) * KST + jloc] = kv.x;
                KV[(d4 + 1) * KST + jloc] = kv.y;
                KV[(d4 + 2) * KST + jloc] = kv.z;
                KV[(d4 + 3) * KST + jloc] = kv.w;
            }
        }
        __syncthreads();

        if (jg * 8 < W) {
            float acc[4][8];
#pragma unroll
            for (int i = 0; i < 4; i++)
#pragma unroll
                for (int e = 0; e < 8; e++) acc[i][e] = 0.f;

#pragma unroll 4
            for (int d4 = 0; d4 < HD; d4 += 4) {
                float qa[16];
#pragma unroll
                for (int i = 0; i < 4; i++)
                    *(float4*)&qa[i * 4] =
                        *(const float4*)&Qs[(qg * 4 + i) * VST + d4];
#pragma unroll
                for (int dd = 0; dd < 4; dd++) {
                    const float* kr = &KV[(d4 + dd) * KST + jg * 8];
                    float4 k0 = *(const float4*)kr;
                    float4 k1 = *(const float4*)(kr + 4);
                    float kv8[8] = {k0.x, k0.y, k0.z, k0.w,
                                    k1.x, k1.y, k1.z, k1.w};
#pragma unroll
                    for (int i = 0; i < 4; i++) {
                        float qv = qa[i * 4 + dd];
#pragma unroll
                        for (int e = 0; e < 8; e++)
                            acc[i][e] = fmaf(qv, kv8[e], acc[i][e]);
                    }
                }
            }
            // exp + band mask + float4 store
            const int cbase = cb + jg * 8;
#pragma unroll
            for (int i = 0; i < 4; i++) {
                int qi = qg * 4 + i;
                float o[8];
#pragma unroll
                for (int e = 0; e < 8; e++) {
                    int w = cbase + e - qi;
                    o[e] = ((unsigned)w < WIN) ? __expf(acc[i][e] * 0.125f) : 0.f;
                }
                float* dst = &S[qi * SST + cbase];
                *(float4*)dst       = *(float4*)&o[0];
                *(float4*)(dst + 4) = *(float4*)&o[4];
            }
        }
    }
    __syncthreads();

    // ======================= row sums -> sinv =======================
    {
        int rbase = wv * 4;
#pragma unroll
        for (int rr = 0; rr < 4; rr++) {
            int row = rbase + rr;
            float s = 0.f;
            for (int c = lane; c < COV; c += 32) s += S[row * SST + c];
#pragma unroll
            for (int o = 16; o; o >>= 1) s += __shfl_xor_sync(0xFFFFFFFFu, s, o);
            if (lane == 0) sinv[row] = 1.f / s;
        }
    }
    __syncthreads();

    // ======================= probs write =======================
    if (write_probs) {
        for (int idx = t; idx < QT * WIN; idx += 256) {
            int qi = idx >> 9, w = idx & (WIN - 1);
            probs[((size_t)h * S_LEN + q0 + qi) * WIN + w] =
                S[qi * SST + qi + w] * sinv[qi];
        }
    }

    // ======================= PV phase =======================
    // Thread tile: 4 queries x 8 dims, 4-way j-split (adjacent lanes).
    const int pqg = wv;                // 4 queries
    const int pdg = (lane >> 2) & 7;   // 8-dim group
    const int pjs = lane & 3;          // j split

    float acc[4][8];
#pragma unroll
    for (int i = 0; i < 4; i++)
#pragma unroll
        for (int e = 0; e < 8; e++) acc[i][e] = 0.f;

    for (int vc = 0; vc < 5; vc++) {
        const int vb = vc << 7;
        const int W  = (vc == 4) ? 32 : 128;
        __syncthreads();
        // load V chunk row-major: KV[j][d], zero OOB keys
        for (int r = 0; r < 4; r++) {
            int j = r * 32 + (t >> 3);
            if (j >= W) break;
            int key = kmin + vb + j;
            int d4  = (t & 7) * 8;
            float4 v0, v1;
            if (key >= 0 && key < S_LEN) {
                const float* src = &g_v[(size_t)key * HID + hoff + d4];
                v0 = *(const float4*)src;
                v1 = *(const float4*)(src + 4);
            } else {
                v0 = v1 = make_float4(0.f, 0.f, 0.f, 0.f);
            }
            *(float4*)&KV[j * VST + d4]     = v0;
            *(float4*)&KV[j * VST + d4 + 4] = v1;
        }
        __syncthreads();

        const int U = W >> 2;
        for (int u = 0; u < U; u++) {
            int j = pjs + (u << 2);
            int c = vb + j;
            const float* vr = &KV[j * VST + pdg * 8];
            float4 v0 = *(const float4*)vr;
            float4 v1 = *(const float4*)(vr + 4);
            float vv[8] = {v0.x, v0.y, v0.z, v0.w, v1.x, v1.y, v1.z, v1.w};
#pragma unroll
            for (int i = 0; i < 4; i++) {
                float p = S[(pqg * 4 + i) * SST + c];
#pragma unroll
                for (int e = 0; e < 8; e++)
                    acc[i][e] = fmaf(p, vv[e], acc[i][e]);
            }
        }
    }

    // reduce over the 4 j-split lanes (adjacent in warp)
#pragma unroll
    for (int i = 0; i < 4; i++)
#pragma unroll
        for (int e = 0; e < 8; e++) {
            acc[i][e] += __shfl_xor_sync(0xFFFFFFFFu, acc[i][e], 1);
            acc[i][e] += __shfl_xor_sync(0xFFFFFFFFu, acc[i][e], 2);
        }

    if (pjs == 0) {
#pragma unroll
        for (int i = 0; i < 4; i++) {
            int qi = pqg * 4 + i;
            float iv = sinv[qi];
            float4 o0 = make_float4(acc[i][0] * iv, acc[i][1] * iv,
                                    acc[i][2] * iv, acc[i][3] * iv);
            float4 o1 = make_float4(acc[i][4] * iv, acc[i][5] * iv,
                                    acc[i][6] * iv, acc[i][7] * iv);
            float* dst = &g_ctx[(size_t)(q0 + qi) * HID + hoff + pdg * 8];
            *(float4*)dst       = o0;
            *(float4*)(dst + 4) = o1;
        }
    }
}

// ============================================================================
extern "C" void kernel_launch(void* const* d_in, const int* in_sizes, int n_in,
                              void* d_out, int out_size)
{
    const float* X  = (const float*)d_in[0];
    const float* Wq = (const float*)d_in[1];
    const float* bq = (const float*)d_in[2];
    const float* Wk = (const float*)d_in[3];
    const float* bk = (const float*)d_in[4];
    const float* Wv = (const float*)d_in[5];
    const float* bv = (const float*)d_in[6];
    const float* Wo = (const float*)d_in[7];
    const float* bo = (const float*)d_in[8];

    float* out = (float*)d_out;
    const size_t OUT_ELEMS   = (size_t)S_LEN * HID;
    const size_t PROBS_ELEMS = (size_t)NH * S_LEN * WIN;
    float* probs = out + OUT_ELEMS;
    int write_probs = ((size_t)out_size >= OUT_ELEMS + PROBS_ELEMS) ? 1 : 0;

    cudaFuncSetAttribute(attn_kernel,
                         cudaFuncAttributeMaxDynamicSharedMemorySize,
                         SMEM_FLOATS * (int)sizeof(float));

    dim3 ggrid(HID / 128, S_LEN / 128);
    sgemm_bias<<<ggrid, 256>>>(X, 0, Wq, bq, nullptr, 1, S_LEN, HID, HID);
    sgemm_bias<<<ggrid, 256>>>(X, 0, Wk, bk, nullptr, 2, S_LEN, HID, HID);
    sgemm_bias<<<ggrid, 256>>>(X, 0, Wv, bv, nullptr, 3, S_LEN, HID, HID);

    dim3 agrid(S_LEN / QT, NH);
    attn_kernel<<<agrid, 256, SMEM_FLOATS * sizeof(float)>>>(probs, write_probs);

    sgemm_bias<<<ggrid, 256>>>(nullptr, 4, Wo, bo, out, 0, S_LEN, HID, HID);
}

// round 8
// speedup vs baseline: 1.8037x; 1.4086x over previous
#include <cuda_runtime.h>
#include <cuda_bf16.h>
#include <cstdint>

#define S_LEN 4096
#define HID   1024
#define NH    16
#define HD    64
#define WIN   512
#define HALF  256
#define QT    32
#define COV   544
#define SST   548
#define KST   268
#define VST   68
#define GK    1024
#define GN    1024

// ---- scratch (no cudaMalloc allowed); referenced only from device code ----
__device__ float g_q[S_LEN * HID];
__device__ float g_k[S_LEN * HID];
__device__ float g_v[S_LEN * HID];
__device__ float g_ctx[S_LEN * HID];
// bf16 split activations (X, later ctx) and transposed split weights [N,K]
__device__ __nv_bfloat16 g_xh[S_LEN * HID];
__device__ __nv_bfloat16 g_xl[S_LEN * HID];
__device__ __nv_bfloat16 g_wth[4 * HID * HID];
__device__ __nv_bfloat16 g_wtl[4 * HID * HID];

__device__ __forceinline__ float* buf_ptr(int tag, float* ext) {
    switch (tag) {
        case 1: return g_q;
        case 2: return g_k;
        case 3: return g_v;
        case 4: return g_ctx;
        default: return ext;
    }
}

__device__ __forceinline__ uint32_t smem_u32(const void* p) {
    uint32_t a;
    asm("{ .reg .u64 t; cvta.to.shared.u64 t, %1; cvt.u32.u64 %0, t; }"
        : "=r"(a) : "l"(p));
    return a;
}

#define CP16(dst, src) \
    asm volatile("cp.async.cg.shared.global [%0], [%1], 16;" \
                 :: "r"(dst), "l"(src) : "memory")
#define CP_COMMIT() asm volatile("cp.async.commit_group;" ::: "memory")
#define CP_WAIT1()  asm volatile("cp.async.wait_group 1;" ::: "memory")
#define CP_WAIT0()  asm volatile("cp.async.wait_group 0;" ::: "memory")

#define LDSM4(r, a) \
    asm volatile("ldmatrix.sync.aligned.m8n8.x4.shared.b16 {%0,%1,%2,%3}, [%4];" \
                 : "=r"((r)[0]), "=r"((r)[1]), "=r"((r)[2]), "=r"((r)[3]) \
                 : "r"(a))

#define MMA16816(d, a, b0, b1) \
    asm volatile("mma.sync.aligned.m16n8k16.row.col.f32.bf16.bf16.f32 " \
                 "{%0,%1,%2,%3}, {%4,%5,%6,%7}, {%8,%9}, {%0,%1,%2,%3};" \
                 : "+f"((d)[0]), "+f"((d)[1]), "+f"((d)[2]), "+f"((d)[3]) \
                 : "r"((a)[0]), "r"((a)[1]), "r"((a)[2]), "r"((a)[3]), \
                   "r"(b0), "r"(b1))

__device__ __forceinline__ void split_bf16(float v, __nv_bfloat16& h,
                                           __nv_bfloat16& l) {
    h = __float2bfloat16(v);
    l = __float2bfloat16(v - __bfloat162float(h));
}

// ============================================================================
// convert activations (X or g_ctx) -> g_xh/g_xl.  1M float4s.
// ============================================================================
__global__ __launch_bounds__(256)
void conv_act(const float* __restrict__ src_ext, int tag)
{
    const float* src = (tag == 4) ? g_ctx : src_ext;
    size_t i = (size_t)blockIdx.x * 256 + threadIdx.x;   // float4 index
    float4 v = *(const float4*)(src + i * 4);
    __nv_bfloat16 h[4], l[4];
    split_bf16(v.x, h[0], l[0]); split_bf16(v.y, h[1], l[1]);
    split_bf16(v.z, h[2], l[2]); split_bf16(v.w, h[3], l[3]);
    uint2 hp, lp;
    hp.x = ((uint32_t)__bfloat16_as_ushort(h[1]) << 16) | __bfloat16_as_ushort(h[0]);
    hp.y = ((uint32_t)__bfloat16_as_ushort(h[3]) << 16) | __bfloat16_as_ushort(h[2]);
    lp.x = ((uint32_t)__bfloat16_as_ushort(l[1]) << 16) | __bfloat16_as_ushort(l[0]);
    lp.y = ((uint32_t)__bfloat16_as_ushort(l[3]) << 16) | __bfloat16_as_ushort(l[2]);
    *(uint2*)&g_xh[i * 4] = hp;
    *(uint2*)&g_xl[i * 4] = lp;
}

// ============================================================================
// convert + transpose weight W[K,N] -> g_wth/g_wtl[N,K] at offset woff.
// 32x32 tiles, block (32,8).
// ============================================================================
__global__ __launch_bounds__(256)
void conv_w_t(const float* __restrict__ W, int woff)
{
    __shared__ float tile[32][33];
    const int tx = threadIdx.x, ty = threadIdx.y;
#pragma unroll
    for (int j = 0; j < 4; j++)
        tile[ty + 8 * j][tx] =
            W[(size_t)(blockIdx.y * 32 + ty + 8 * j) * HID + blockIdx.x * 32 + tx];
    __syncthreads();
#pragma unroll
    for (int j = 0; j < 4; j++) {
        float v = tile[tx][ty + 8 * j];
        __nv_bfloat16 h, l;
        split_bf16(v, h, l);
        size_t o = (size_t)woff +
                   (size_t)(blockIdx.x * 32 + ty + 8 * j) * HID + blockIdx.y * 32 + tx;
        g_wth[o] = h;
        g_wtl[o] = l;
    }
}

// ============================================================================
// HMMA split-bf16 GEMM: C[4096,1024] = X @ W + bias, A=g_xh/g_xl [M,K],
// B=g_wth/g_wtl+woff [N,K]. Tile 128x128, BK=32, cp.async double buffer.
// smem halves layout per buffer (stride AST=40): Ah 0 | Al 5120 | Bh 10240 | Bl 15360
// buffer bytes 40960, two buffers = 81920.
// ============================================================================
#define AST  40
#define BUFB 40960

__global__ __launch_bounds__(256, 2)
void hgemm(int woff, const float* __restrict__ bias,
           float* __restrict__ Cext, int Ctag)
{
    extern __shared__ __align__(128) char hsm[];
    float* C = buf_ptr(Ctag, Cext);

    const int t = threadIdx.x, wid = t >> 5, lane = t & 31;
    const int n0 = blockIdx.x * 128, m0 = blockIdx.y * 128;
    const uint32_t sb = smem_u32(hsm);

    // staging: thread -> (row = t/2, 32B segment = t&1)
    const int lrow = t >> 1;
    const int lseg = (t & 1) * 16;              // halves
    const __nv_bfloat16* gah = g_xh + (size_t)(m0 + lrow) * GK + lseg;
    const __nv_bfloat16* gal = g_xl + (size_t)(m0 + lrow) * GK + lseg;
    const __nv_bfloat16* gbh = g_wth + woff + (size_t)(n0 + lrow) * GK + lseg;
    const __nv_bfloat16* gbl = g_wtl + woff + (size_t)(n0 + lrow) * GK + lseg;
    const uint32_t sA = sb + (uint32_t)(lrow * AST + lseg) * 2;

    const int warp_m = wid & 3, warp_n = wid >> 2;
    const int l16 = lane & 15, lh8 = (lane >> 4) * 8;

    float acc[2][8][4];
#pragma unroll
    for (int i = 0; i < 2; i++)
#pragma unroll
        for (int j = 0; j < 8; j++)
#pragma unroll
            for (int e = 0; e < 4; e++) acc[i][j][e] = 0.f;

#define ISSUE(c) do {                                                        \
    const uint32_t d = sA + ((c) & 1) * BUFB;                                \
    const int ko = (c) * 32;                                                 \
    CP16(d,              gah + ko); CP16(d + 16,             gah + ko + 8);  \
    CP16(d + 10240,      gal + ko); CP16(d + 10240 + 16,     gal + ko + 8);  \
    CP16(d + 20480,      gbh + ko); CP16(d + 20480 + 16,     gbh + ko + 8);  \
    CP16(d + 30720,      gbl + ko); CP16(d + 30720 + 16,     gbl + ko + 8);  \
    CP_COMMIT();                                                             \
} while (0)

    ISSUE(0);
    for (int c = 0; c < 32; c++) {
        if (c + 1 < 32) { ISSUE(c + 1); CP_WAIT1(); }
        else            { CP_WAIT0(); }
        __syncthreads();

        const uint32_t ab = sb + (c & 1) * BUFB;
        const uint32_t bb = ab + 20480;
#pragma unroll
        for (int ks = 0; ks < 32; ks += 16) {
            uint32_t ah[2][4], al[2][4];
#pragma unroll
            for (int mf = 0; mf < 2; mf++) {
                uint32_t ad = ab +
                    (uint32_t)((warp_m * 32 + mf * 16 + l16) * AST + ks + lh8) * 2;
                LDSM4(ah[mf], ad);
                LDSM4(al[mf], ad + 10240);
            }
#pragma unroll
            for (int nf = 0; nf < 4; nf++) {
                uint32_t bh[4], bl[4];
                uint32_t bd = bb +
                    (uint32_t)((warp_n * 64 + nf * 16 + l16) * AST + ks + lh8) * 2;
                LDSM4(bh, bd);
                LDSM4(bl, bd + 10240);
#pragma unroll
                for (int mf = 0; mf < 2; mf++)
#pragma unroll
                    for (int j = 0; j < 2; j++) {
                        float* d = acc[mf][nf * 2 + j];
                        MMA16816(d, ah[mf], bh[j], bh[j + 2]);
                        MMA16816(d, ah[mf], bl[j], bl[j + 2]);
                        MMA16816(d, al[mf], bh[j], bh[j + 2]);
                    }
            }
        }
        __syncthreads();
    }

    // epilogue: d-frag thread mapping (m = t/4 [+8], n = 2*(t%4))
    const int er = lane >> 2, ec = (lane & 3) * 2;
#pragma unroll
    for (int mf = 0; mf < 2; mf++)
#pragma unroll
        for (int n8 = 0; n8 < 8; n8++) {
            int m = m0 + warp_m * 32 + mf * 16 + er;
            int n = n0 + warp_n * 64 + n8 * 8 + ec;
            float bx = bias[n], by = bias[n + 1];
            float* a4 = acc[mf][n8];
            *(float2*)&C[(size_t)m * GN + n] =
                make_float2(a4[0] + bx, a4[1] + by);
            *(float2*)&C[(size_t)(m + 8) * GN + n] =
                make_float2(a4[2] + bx, a4[3] + by);
        }
#undef ISSUE
}

// ============================================================================
// Sliding-window attention (unchanged from the 1468us passing version)
// ============================================================================
#define SM_S   0
#define SM_KV  17536
#define SM_Q   34688
#define SM_INV 36864
#define SMEM_FLOATS 36896

__global__ __launch_bounds__(256)
void attn_kernel(float* __restrict__ probs, int write_probs)
{
    extern __shared__ float sm[];
    float* S    = sm + SM_S;
    float* KV   = sm + SM_KV;
    float* Qs   = sm + SM_Q;
    float* sinv = sm + SM_INV;

    const int t    = threadIdx.x;
    const int lane = t & 31;
    const int wv   = t >> 5;
    const int q0   = blockIdx.x * QT;
    const int h    = blockIdx.y;
    const int hoff = h * HD;
    const int kmin = q0 - HALF;

#pragma unroll
    for (int r = 0; r < 2; r++) {
        int f4 = r * 256 + t;
        int qi = f4 >> 4;
        int d4 = (f4 & 15) << 2;
        *(float4*)&Qs[qi * VST + d4] =
            *(const float4*)&g_q[(size_t)(q0 + qi) * HID + hoff + d4];
    }

    const int qg  = wv;
    const int jg  = lane;
    const int lkk = lane >> 2;
    const int ld4 = (lane & 3) << 2;

    for (int cc = 0; cc < 3; cc++) {
        const int cb = cc << 8;
        const int W  = (cc == 2) ? 32 : 256;
        __syncthreads();
        for (int kg = 0; kg < 4; kg++) {
            int jloc = kg * 64 + wv * 8 + lkk;
            if (jloc >= W) break;
            int key = kmin + cb + jloc;
            const bool ok = (key >= 0 && key < S_LEN);
            const float* src = &g_k[(size_t)key * HID + hoff];
#pragma unroll
            for (int dq = 0; dq < 4; dq++) {
                int d4 = dq * 16 + ld4;
                float4 kv = ok ? *(const float4*)(src + d4)
                               : make_float4(0.f, 0.f, 0.f, 0.f);
                KV[(d4 + 0) * KST + jloc] = kv.x;
                KV[(d4 + 1) * KST + jloc] = kv.y;
                KV[(d4 + 2) * KST + jloc] = kv.z;
                KV[(d4 + 3) * KST + jloc] = kv.w;
            }
        }
        __syncthreads();

        if (jg * 8 < W) {
            float acc[4][8];
#pragma unroll
            for (int i = 0; i < 4; i++)
#pragma unroll
                for (int e = 0; e < 8; e++) acc[i][e] = 0.f;

#pragma unroll 4
            for (int d4 = 0; d4 < HD; d4 += 4) {
                float qa[16];
#pragma unroll
                for (int i = 0; i < 4; i++)
                    *(float4*)&qa[i * 4] =
                        *(const float4*)&Qs[(qg * 4 + i) * VST + d4];
#pragma unroll
                for (int dd = 0; dd < 4; dd++) {
                    const float* kr = &KV[(d4 + dd) * KST + jg * 8];
                    float4 k0 = *(const float4*)kr;
                    float4 k1 = *(const float4*)(kr + 4);
                    float kv8[8] = {k0.x, k0.y, k0.z, k0.w,
                                    k1.x, k1.y, k1.z, k1.w};
#pragma unroll
                    for (int i = 0; i < 4; i++) {
                        float qv = qa[i * 4 + dd];
#pragma unroll
                        for (int e = 0; e < 8; e++)
                            acc[i][e] = fmaf(qv, kv8[e], acc[i][e]);
                    }
                }
            }
            const int cbase = cb + jg * 8;
#pragma unroll
            for (int i = 0; i < 4; i++) {
                int qi = qg * 4 + i;
                float o[8];
#pragma unroll
                for (int e = 0; e < 8; e++) {
                    int w = cbase + e - qi;
                    o[e] = ((unsigned)w < WIN) ? __expf(acc[i][e] * 0.125f) : 0.f;
                }
                float* dst = &S[qi * SST + cbase];
                *(float4*)dst       = *(float4*)&o[0];
                *(float4*)(dst + 4) = *(float4*)&o[4];
            }
        }
    }
    __syncthreads();

    {
        int rbase = wv * 4;
#pragma unroll
        for (int rr = 0; rr < 4; rr++) {
            int row = rbase + rr;
            float s = 0.f;
            for (int c = lane; c < COV; c += 32) s += S[row * SST + c];
#pragma unroll
            for (int o = 16; o; o >>= 1) s += __shfl_xor_sync(0xFFFFFFFFu, s, o);
            if (lane == 0) sinv[row] = 1.f / s;
        }
    }
    __syncthreads();

    if (write_probs) {
        for (int idx = t; idx < QT * WIN; idx += 256) {
            int qi = idx >> 9, w = idx & (WIN - 1);
            probs[((size_t)h * S_LEN + q0 + qi) * WIN + w] =
                S[qi * SST + qi + w] * sinv[qi];
        }
    }

    const int pqg = wv;
    const int pdg = (lane >> 2) & 7;
    const int pjs = lane & 3;

    float acc[4][8];
#pragma unroll
    for (int i = 0; i < 4; i++)
#pragma unroll
        for (int e = 0; e < 8; e++) acc[i][e] = 0.f;

    for (int vc = 0; vc < 5; vc++) {
        const int vb = vc << 7;
        const int W  = (vc == 4) ? 32 : 128;
        __syncthreads();
        for (int r = 0; r < 4; r++) {
            int j = r * 32 + (t >> 3);
            if (j >= W) break;
            int key = kmin + vb + j;
            int d4  = (t & 7) * 8;
            float4 v0, v1;
            if (key >= 0 && key < S_LEN) {
                const float* src = &g_v[(size_t)key * HID + hoff + d4];
                v0 = *(const float4*)src;
                v1 = *(const float4*)(src + 4);
            } else {
                v0 = v1 = make_float4(0.f, 0.f, 0.f, 0.f);
            }
            *(float4*)&KV[j * VST + d4]     = v0;
            *(float4*)&KV[j * VST + d4 + 4] = v1;
        }
        __syncthreads();

        const int U = W >> 2;
        for (int u = 0; u < U; u++) {
            int j = pjs + (u << 2);
            int c = vb + j;
            const float* vr = &KV[j * VST + pdg * 8];
            float4 v0 = *(const float4*)vr;
            float4 v1 = *(const float4*)(vr + 4);
            float vv[8] = {v0.x, v0.y, v0.z, v0.w, v1.x, v1.y, v1.z, v1.w};
#pragma unroll
            for (int i = 0; i < 4; i++) {
                float p = S[(pqg * 4 + i) * SST + c];
#pragma unroll
                for (int e = 0; e < 8; e++)
                    acc[i][e] = fmaf(p, vv[e], acc[i][e]);
            }
        }
    }

#pragma unroll
    for (int i = 0; i < 4; i++)
#pragma unroll
        for (int e = 0; e < 8; e++) {
            acc[i][e] += __shfl_xor_sync(0xFFFFFFFFu, acc[i][e], 1);
            acc[i][e] += __shfl_xor_sync(0xFFFFFFFFu, acc[i][e], 2);
        }

    if (pjs == 0) {
#pragma unroll
        for (int i = 0; i < 4; i++) {
            int qi = pqg * 4 + i;
            float iv = sinv[qi];
            float4 o0 = make_float4(acc[i][0] * iv, acc[i][1] * iv,
                                    acc[i][2] * iv, acc[i][3] * iv);
            float4 o1 = make_float4(acc[i][4] * iv, acc[i][5] * iv,
                                    acc[i][6] * iv, acc[i][7] * iv);
            float* dst = &g_ctx[(size_t)(q0 + qi) * HID + hoff + pdg * 8];
            *(float4*)dst       = o0;
            *(float4*)(dst + 4) = o1;
        }
    }
}

// ============================================================================
extern "C" void kernel_launch(void* const* d_in, const int* in_sizes, int n_in,
                              void* d_out, int out_size)
{
    const float* X  = (const float*)d_in[0];
    const float* Wq = (const float*)d_in[1];
    const float* bq = (const float*)d_in[2];
    const float* Wk = (const float*)d_in[3];
    const float* bk = (const float*)d_in[4];
    const float* Wv = (const float*)d_in[5];
    const float* bv = (const float*)d_in[6];
    const float* Wo = (const float*)d_in[7];
    const float* bo = (const float*)d_in[8];

    float* out = (float*)d_out;
    const size_t OUT_ELEMS   = (size_t)S_LEN * HID;
    const size_t PROBS_ELEMS = (size_t)NH * S_LEN * WIN;
    float* probs = out + OUT_ELEMS;
    int write_probs = ((size_t)out_size >= OUT_ELEMS + PROBS_ELEMS) ? 1 : 0;

    cudaFuncSetAttribute(attn_kernel,
                         cudaFuncAttributeMaxDynamicSharedMemorySize,
                         SMEM_FLOATS * (int)sizeof(float));
    cudaFuncSetAttribute(hgemm,
                         cudaFuncAttributeMaxDynamicSharedMemorySize, 2 * BUFB);

    // split-convert X and all 4 weights (transposed)
    conv_act<<<(S_LEN * HID) / 1024, 256>>>(X, 0);
    dim3 ct(32, 8), cg(HID / 32, HID / 32);
    conv_w_t<<<cg, ct>>>(Wq, 0);
    conv_w_t<<<cg, ct>>>(Wk, HID * HID);
    conv_w_t<<<cg, ct>>>(Wv, 2 * HID * HID);
    conv_w_t<<<cg, ct>>>(Wo, 3 * HID * HID);

    dim3 ggrid(GN / 128, S_LEN / 128);   // (8, 32)
    hgemm<<<ggrid, 256, 2 * BUFB>>>(0,             bq, nullptr, 1);
    hgemm<<<ggrid, 256, 2 * BUFB>>>(HID * HID,     bk, nullptr, 2);
    hgemm<<<ggrid, 256, 2 * BUFB>>>(2 * HID * HID, bv, nullptr, 3);

    dim3 agrid(S_LEN / QT, NH);
    attn_kernel<<<agrid, 256, SMEM_FLOATS * sizeof(float)>>>(probs, write_probs);

    conv_act<<<(S_LEN * HID) / 1024, 256>>>(nullptr, 4);
    hgemm<<<ggrid, 256, 2 * BUFB>>>(3 * HID * HID, bo, out, 0);
}

// round 9
// speedup vs baseline: 2.4669x; 1.3677x over previous
#include <cuda_runtime.h>
#include <cuda_bf16.h>
#include <cstdint>

#define S_LEN 4096
#define HID   1024
#define NH    16
#define HD    64
#define WIN   512
#define HALF  256
#define QT    32
#define COV   544
#define GK    1024
#define GN    1024

// ---- scratch (no cudaMalloc allowed); referenced only from device code ----
__device__ float g_q[S_LEN * HID];
__device__ float g_k[S_LEN * HID];
__device__ float g_v[S_LEN * HID];
__device__ float g_ctx[S_LEN * HID];
__device__ __nv_bfloat16 g_xh[S_LEN * HID];
__device__ __nv_bfloat16 g_xl[S_LEN * HID];
__device__ __nv_bfloat16 g_wth[4 * HID * HID];
__device__ __nv_bfloat16 g_wtl[4 * HID * HID];

__device__ __forceinline__ float* buf_ptr(int tag, float* ext) {
    switch (tag) {
        case 1: return g_q;
        case 2: return g_k;
        case 3: return g_v;
        case 4: return g_ctx;
        default: return ext;
    }
}

__device__ __forceinline__ uint32_t smem_u32(const void* p) {
    uint32_t a;
    asm("{ .reg .u64 t; cvta.to.shared.u64 t, %1; cvt.u32.u64 %0, t; }"
        : "=r"(a) : "l"(p));
    return a;
}

#define CP16(dst, src) \
    asm volatile("cp.async.cg.shared.global [%0], [%1], 16;" \
                 :: "r"(dst), "l"(src) : "memory")
#define CP_COMMIT() asm volatile("cp.async.commit_group;" ::: "memory")
#define CP_WAIT1()  asm volatile("cp.async.wait_group 1;" ::: "memory")
#define CP_WAIT0()  asm volatile("cp.async.wait_group 0;" ::: "memory")

#define LDSM4(r, a) \
    asm volatile("ldmatrix.sync.aligned.m8n8.x4.shared.b16 {%0,%1,%2,%3}, [%4];" \
                 : "=r"((r)[0]), "=r"((r)[1]), "=r"((r)[2]), "=r"((r)[3]) \
                 : "r"(a))

#define MMA16816(d, a, b0, b1) \
    asm volatile("mma.sync.aligned.m16n8k16.row.col.f32.bf16.bf16.f32 " \
                 "{%0,%1,%2,%3}, {%4,%5,%6,%7}, {%8,%9}, {%0,%1,%2,%3};" \
                 : "+f"((d)[0]), "+f"((d)[1]), "+f"((d)[2]), "+f"((d)[3]) \
                 : "r"((a)[0]), "r"((a)[1]), "r"((a)[2]), "r"((a)[3]), \
                   "r"(b0), "r"(b1))

__device__ __forceinline__ void split_bf16(float v, __nv_bfloat16& h,
                                           __nv_bfloat16& l) {
    h = __float2bfloat16(v);
    l = __float2bfloat16(v - __bfloat162float(h));
}
__device__ __forceinline__ uint32_t pk2(__nv_bfloat16 a, __nv_bfloat16 b) {
    return ((uint32_t)__bfloat16_as_ushort(b) << 16) | __bfloat16_as_ushort(a);
}
__device__ __forceinline__ void sp2(float a, float b, uint32_t& hp, uint32_t& lp) {
    __nv_bfloat16 ha, la, hb, lb;
    split_bf16(a, ha, la);
    split_bf16(b, hb, lb);
    hp = pk2(ha, hb);
    lp = pk2(la, lb);
}

// ============================================================================
// convert activations (X or g_ctx) -> g_xh/g_xl
// ============================================================================
__global__ __launch_bounds__(256)
void conv_act(const float* __restrict__ src_ext, int tag)
{
    const float* src = (tag == 4) ? g_ctx : src_ext;
    size_t i = (size_t)blockIdx.x * 256 + threadIdx.x;
    float4 v = *(const float4*)(src + i * 4);
    uint2 hp, lp;
    sp2(v.x, v.y, hp.x, lp.x);
    sp2(v.z, v.w, hp.y, lp.y);
    *(uint2*)&g_xh[i * 4] = hp;
    *(uint2*)&g_xl[i * 4] = lp;
}

// ============================================================================
// convert + transpose weight W[K,N] -> g_wth/g_wtl[N,K] at offset woff
// ============================================================================
__global__ __launch_bounds__(256)
void conv_w_t(const float* __restrict__ W, int woff)
{
    __shared__ float tile[32][33];
    const int tx = threadIdx.x, ty = threadIdx.y;
#pragma unroll
    for (int j = 0; j < 4; j++)
        tile[ty + 8 * j][tx] =
            W[(size_t)(blockIdx.y * 32 + ty + 8 * j) * HID + blockIdx.x * 32 + tx];
    __syncthreads();
#pragma unroll
    for (int j = 0; j < 4; j++) {
        float v = tile[tx][ty + 8 * j];
        __nv_bfloat16 h, l;
        split_bf16(v, h, l);
        size_t o = (size_t)woff +
                   (size_t)(blockIdx.x * 32 + ty + 8 * j) * HID + blockIdx.y * 32 + tx;
        g_wth[o] = h;
        g_wtl[o] = l;
    }
}

// ============================================================================
// HMMA split-bf16 GEMM (unchanged from the 1042us passing version)
// ============================================================================
#define AST  40
#define BUFB 40960

__global__ __launch_bounds__(256, 2)
void hgemm(int woff, const float* __restrict__ bias,
           float* __restrict__ Cext, int Ctag)
{
    extern __shared__ __align__(128) char hsm[];
    float* C = buf_ptr(Ctag, Cext);

    const int t = threadIdx.x, wid = t >> 5, lane = t & 31;
    const int n0 = blockIdx.x * 128, m0 = blockIdx.y * 128;
    const uint32_t sb = smem_u32(hsm);

    const int lrow = t >> 1;
    const int lseg = (t & 1) * 16;
    const __nv_bfloat16* gah = g_xh + (size_t)(m0 + lrow) * GK + lseg;
    const __nv_bfloat16* gal = g_xl + (size_t)(m0 + lrow) * GK + lseg;
    const __nv_bfloat16* gbh = g_wth + woff + (size_t)(n0 + lrow) * GK + lseg;
    const __nv_bfloat16* gbl = g_wtl + woff + (size_t)(n0 + lrow) * GK + lseg;
    const uint32_t sA = sb + (uint32_t)(lrow * AST + lseg) * 2;

    const int warp_m = wid & 3, warp_n = wid >> 2;
    const int l16 = lane & 15, lh8 = (lane >> 4) * 8;

    float acc[2][8][4];
#pragma unroll
    for (int i = 0; i < 2; i++)
#pragma unroll
        for (int j = 0; j < 8; j++)
#pragma unroll
            for (int e = 0; e < 4; e++) acc[i][j][e] = 0.f;

#define ISSUE(c) do {                                                        \
    const uint32_t d = sA + ((c) & 1) * BUFB;                                \
    const int ko = (c) * 32;                                                 \
    CP16(d,              gah + ko); CP16(d + 16,             gah + ko + 8);  \
    CP16(d + 10240,      gal + ko); CP16(d + 10240 + 16,     gal + ko + 8);  \
    CP16(d + 20480,      gbh + ko); CP16(d + 20480 + 16,     gbh + ko + 8);  \
    CP16(d + 30720,      gbl + ko); CP16(d + 30720 + 16,     gbl + ko + 8);  \
    CP_COMMIT();                                                             \
} while (0)

    ISSUE(0);
    for (int c = 0; c < 32; c++) {
        if (c + 1 < 32) { ISSUE(c + 1); CP_WAIT1(); }
        else            { CP_WAIT0(); }
        __syncthreads();

        const uint32_t ab = sb + (c & 1) * BUFB;
        const uint32_t bb = ab + 20480;
#pragma unroll
        for (int ks = 0; ks < 32; ks += 16) {
            uint32_t ah[2][4], al[2][4];
#pragma unroll
            for (int mf = 0; mf < 2; mf++) {
                uint32_t ad = ab +
                    (uint32_t)((warp_m * 32 + mf * 16 + l16) * AST + ks + lh8) * 2;
                LDSM4(ah[mf], ad);
                LDSM4(al[mf], ad + 10240);
            }
#pragma unroll
            for (int nf = 0; nf < 4; nf++) {
                uint32_t bh[4], bl[4];
                uint32_t bd = bb +
                    (uint32_t)((warp_n * 64 + nf * 16 + l16) * AST + ks + lh8) * 2;
                LDSM4(bh, bd);
                LDSM4(bl, bd + 10240);
#pragma unroll
                for (int mf = 0; mf < 2; mf++)
#pragma unroll
                    for (int j = 0; j < 2; j++) {
                        float* d = acc[mf][nf * 2 + j];
                        MMA16816(d, ah[mf], bh[j], bh[j + 2]);
                        MMA16816(d, ah[mf], bl[j], bl[j + 2]);
                        MMA16816(d, al[mf], bh[j], bh[j + 2]);
                    }
            }
        }
        __syncthreads();
    }

    const int er = lane >> 2, ec = (lane & 3) * 2;
#pragma unroll
    for (int mf = 0; mf < 2; mf++)
#pragma unroll
        for (int n8 = 0; n8 < 8; n8++) {
            int m = m0 + warp_m * 32 + mf * 16 + er;
            int n = n0 + warp_n * 64 + n8 * 8 + ec;
            float bx = bias[n], by = bias[n + 1];
            float* a4 = acc[mf][n8];
            *(float2*)&C[(size_t)m * GN + n] =
                make_float2(a4[0] + bx, a4[1] + by);
            *(float2*)&C[(size_t)(m + 8) * GN + n] =
                make_float2(a4[2] + bx, a4[3] + by);
        }
#undef ISSUE
}

// ============================================================================
// HMMA sliding-window attention. Block = (32 queries, head), 8 warps.
// P[qi][c] = exp(score) (band-masked to 0) in split bf16 smem; PV via HMMA.
// smem layout (bytes):
//   Ph 0       32x552 halves   35328
//   Pl 35328                   35328
//   KV 70656   K: Kh 64x72, Kl (+9216)  /  V: Vh[d][key] 64x72, Vl (+9216)
//   Qh 89088   32x72 halves 4608 | Ql 93696 4608
//   part 98304 8x32 f32 1024 | sinv 99328 128  -> total 99456
// ============================================================================
#define PSTH  552
#define KSTH  72
#define APHB  0
#define APLB  35328
#define AKVB  70656
#define AQHB  89088
#define AQLB  93696
#define APRT  98304
#define ASNV  99328
#define ASMEM 99456

__global__ __launch_bounds__(256, 2)
void attn_kernel(float* __restrict__ probs, int write_probs)
{
    extern __shared__ __align__(128) char am[];
    const uint32_t sb = smem_u32(am);

    const int t    = threadIdx.x;
    const int lane = t & 31;
    const int w    = t >> 5;
    const int q0   = blockIdx.x * QT;
    const int h    = blockIdx.y;
    const int hoff = h * HD;
    const int kmin = q0 - HALF;

    float* part = (float*)(am + APRT);
    float* sinv = (float*)(am + ASNV);
    part[t] = 0.f;

    // ---- stage Q split: 32 rows x 64 d ----
    if (t < 128) {
        int row = t >> 2, dg = (t & 3) * 16;
        const float4* s4 = (const float4*)&g_q[(size_t)(q0 + row) * HID + hoff + dg];
        uint32_t hp[8], lp[8];
#pragma unroll
        for (int u = 0; u < 4; u++) {
            float4 v = s4[u];
            sp2(v.x, v.y, hp[u * 2], lp[u * 2]);
            sp2(v.z, v.w, hp[u * 2 + 1], lp[u * 2 + 1]);
        }
        uint32_t o = (uint32_t)(row * KSTH + dg) * 2;
        *(uint4*)(am + AQHB + o)      = make_uint4(hp[0], hp[1], hp[2], hp[3]);
        *(uint4*)(am + AQHB + o + 16) = make_uint4(hp[4], hp[5], hp[6], hp[7]);
        *(uint4*)(am + AQLB + o)      = make_uint4(lp[0], lp[1], lp[2], lp[3]);
        *(uint4*)(am + AQLB + o + 16) = make_uint4(lp[4], lp[5], lp[6], lp[7]);
    }
    __syncthreads();

    const int mt  = w & 1;
    const int nb  = (w >> 1) * 16;        // QK: key base within chunk
    const int ds  = w >> 1;               // PV: d strip (*16)
    const int l16 = lane & 15, lh8 = (lane >> 4) * 8;

    // ---- Q fragments (chunk-invariant) ----
    uint32_t qh[4][4], ql[4][4];
#pragma unroll
    for (int ks = 0; ks < 4; ks++) {
        uint32_t ad = sb + AQHB + (uint32_t)((mt * 16 + l16) * KSTH + ks * 16 + lh8) * 2;
        LDSM4(qh[ks], ad);
        LDSM4(ql[ks], ad + (AQLB - AQHB));
    }

    // ======================= QK phase: 9 chunks of 64 (last 32) ============
    float rs0 = 0.f, rs1 = 0.f;
    const int r0 = mt * 16 + (lane >> 2), r1 = r0 + 8;

    for (int cc = 0; cc < 9; cc++) {
        const int cb = cc * 64;
        const int W  = (cc == 8) ? 32 : 64;
        __syncthreads();
        // stage K chunk split: rows = key-local, cols = d
        {
            int row = t >> 2, dg = (t & 3) * 16;
            if (row < W) {
                int key = kmin + cb + row;
                bool ok = (key >= 0 && key < S_LEN);
                uint32_t hp[8], lp[8];
                if (ok) {
                    const float4* s4 =
                        (const float4*)&g_k[(size_t)key * HID + hoff + dg];
#pragma unroll
                    for (int u = 0; u < 4; u++) {
                        float4 v = s4[u];
                        sp2(v.x, v.y, hp[u * 2], lp[u * 2]);
                        sp2(v.z, v.w, hp[u * 2 + 1], lp[u * 2 + 1]);
                    }
                } else {
#pragma unroll
                    for (int u = 0; u < 8; u++) { hp[u] = 0; lp[u] = 0; }
                }
                uint32_t o = (uint32_t)(row * KSTH + dg) * 2;
                *(uint4*)(am + AKVB + o)      = make_uint4(hp[0], hp[1], hp[2], hp[3]);
                *(uint4*)(am + AKVB + o + 16) = make_uint4(hp[4], hp[5], hp[6], hp[7]);
                *(uint4*)(am + AKVB + 9216 + o)      = make_uint4(lp[0], lp[1], lp[2], lp[3]);
                *(uint4*)(am + AKVB + 9216 + o + 16) = make_uint4(lp[4], lp[5], lp[6], lp[7]);
            }
        }
        __syncthreads();

        if (nb < W) {
            float acc[2][4];
#pragma unroll
            for (int j = 0; j < 2; j++)
#pragma unroll
                for (int e = 0; e < 4; e++) acc[j][e] = 0.f;

#pragma unroll
            for (int ks = 0; ks < 4; ks++) {
                uint32_t bh[4], bl[4];
                uint32_t bd = sb + AKVB +
                    (uint32_t)((nb + l16) * KSTH + ks * 16 + lh8) * 2;
                LDSM4(bh, bd);
                LDSM4(bl, bd + 9216);
#pragma unroll
                for (int j = 0; j < 2; j++) {
                    MMA16816(acc[j], qh[ks], bh[j], bh[j + 2]);
                    MMA16816(acc[j], qh[ks], bl[j], bl[j + 2]);
                    MMA16816(acc[j], ql[ks], bh[j], bh[j + 2]);
                }
            }
            // exp + band mask + split-store P + row sums
#pragma unroll
            for (int j = 0; j < 2; j++) {
                int c0 = cb + nb + j * 8 + (lane & 3) * 2;
                float o00 = ((unsigned)(c0 - r0) < WIN)
                            ? __expf(acc[j][0] * 0.125f) : 0.f;
                float o01 = ((unsigned)(c0 + 1 - r0) < WIN)
                            ? __expf(acc[j][1] * 0.125f) : 0.f;
                float o10 = ((unsigned)(c0 - r1) < WIN)
                            ? __expf(acc[j][2] * 0.125f) : 0.f;
                float o11 = ((unsigned)(c0 + 1 - r1) < WIN)
                            ? __expf(acc[j][3] * 0.125f) : 0.f;
                rs0 += o00 + o01;
                rs1 += o10 + o11;
                uint32_t hp, lp;
                sp2(o00, o01, hp, lp);
                *(uint32_t*)(am + APHB + (uint32_t)(r0 * PSTH + c0) * 2) = hp;
                *(uint32_t*)(am + APLB + (uint32_t)(r0 * PSTH + c0) * 2) = lp;
                sp2(o10, o11, hp, lp);
                *(uint32_t*)(am + APHB + (uint32_t)(r1 * PSTH + c0) * 2) = hp;
                *(uint32_t*)(am + APLB + (uint32_t)(r1 * PSTH + c0) * 2) = lp;
            }
        }
    }

    // ---- deterministic row sums ----
    rs0 += __shfl_xor_sync(0xFFFFFFFFu, rs0, 1);
    rs0 += __shfl_xor_sync(0xFFFFFFFFu, rs0, 2);
    rs1 += __shfl_xor_sync(0xFFFFFFFFu, rs1, 1);
    rs1 += __shfl_xor_sync(0xFFFFFFFFu, rs1, 2);
    if ((lane & 3) == 0) {
        part[w * 32 + r0] = rs0;
        part[w * 32 + r1] = rs1;
    }
    __syncthreads();
    if (t < 32) {
        float s = 0.f;
#pragma unroll
        for (int w8 = 0; w8 < 8; w8++) s += part[w8 * 32 + t];
        sinv[t] = 1.f / s;
    }
    __syncthreads();

    // ---- probs write ----
    if (write_probs) {
        float* pr = probs + ((size_t)h * S_LEN + q0) * WIN;
        for (int idx = t; idx < QT * WIN; idx += 256) {
            int qi = idx >> 9, ww = idx & (WIN - 1);
            uint32_t o = (uint32_t)(qi * PSTH + qi + ww) * 2;
            float ph = __bfloat162float(*(__nv_bfloat16*)(am + APHB + o));
            float pl = __bfloat162float(*(__nv_bfloat16*)(am + APLB + o));
            pr[(size_t)qi * WIN + ww] = (ph + pl) * sinv[qi];
        }
    }

    // ======================= PV phase ======================================
    float acc2[2][4];
#pragma unroll
    for (int j = 0; j < 2; j++)
#pragma unroll
        for (int e = 0; e < 4; e++) acc2[j][e] = 0.f;

    for (int cc = 0; cc < 9; cc++) {
        const int cb = cc * 64;
        const int W  = (cc == 8) ? 32 : 64;
        __syncthreads();
        // stage V transposed split: Vh/Vl [d][key-local]
        {
            int keyl = t >> 2, dg = (t & 3) * 16;
            if (keyl < W) {
                int key = kmin + cb + keyl;
                bool ok = (key >= 0 && key < S_LEN);
                const float4* s4 =
                    (const float4*)&g_v[(size_t)key * HID + hoff + dg];
#pragma unroll
                for (int u = 0; u < 4; u++) {
                    float4 v = ok ? s4[u] : make_float4(0.f, 0.f, 0.f, 0.f);
                    float vv[4] = {v.x, v.y, v.z, v.w};
#pragma unroll
                    for (int e = 0; e < 4; e++) {
                        __nv_bfloat16 hh, ll;
                        split_bf16(vv[e], hh, ll);
                        int d = dg + u * 4 + e;
                        uint32_t o = (uint32_t)(d * KSTH + keyl) * 2;
                        *(__nv_bfloat16*)(am + AKVB + o)        = hh;
                        *(__nv_bfloat16*)(am + AKVB + 9216 + o) = ll;
                    }
                }
            }
        }
        __syncthreads();

        const int nks = W >> 4;
        for (int ks = 0; ks < nks; ks++) {
            uint32_t pah[4], pal[4], vbh[4], vbl[4];
            uint32_t pd = sb + APHB +
                (uint32_t)((mt * 16 + l16) * PSTH + cb + ks * 16 + lh8) * 2;
            LDSM4(pah, pd);
            LDSM4(pal, pd + (APLB - APHB));
            uint32_t vd = sb + AKVB +
                (uint32_t)((ds * 16 + l16) * KSTH + ks * 16 + lh8) * 2;
            LDSM4(vbh, vd);
            LDSM4(vbl, vd + 9216);
#pragma unroll
            for (int j = 0; j < 2; j++) {
                MMA16816(acc2[j], pah, vbh[j], vbh[j + 2]);
                MMA16816(acc2[j], pah, vbl[j], vbl[j + 2]);
                MMA16816(acc2[j], pal, vbh[j], vbh[j + 2]);
            }
        }
    }

    // ---- ctx epilogue ----
    {
        float i0 = sinv[r0], i1 = sinv[r1];
#pragma unroll
        for (int j = 0; j < 2; j++) {
            int c = ds * 16 + j * 8 + (lane & 3) * 2;
            *(float2*)&g_ctx[(size_t)(q0 + r0) * HID + hoff + c] =
                make_float2(acc2[j][0] * i0, acc2[j][1] * i0);
            *(float2*)&g_ctx[(size_t)(q0 + r1) * HID + hoff + c] =
                make_float2(acc2[j][2] * i1, acc2[j][3] * i1);
        }
    }
}

// ============================================================================
extern "C" void kernel_launch(void* const* d_in, const int* in_sizes, int n_in,
                              void* d_out, int out_size)
{
    const float* X  = (const float*)d_in[0];
    const float* Wq = (const float*)d_in[1];
    const float* bq = (const float*)d_in[2];
    const float* Wk = (const float*)d_in[3];
    const float* bk = (const float*)d_in[4];
    const float* Wv = (const float*)d_in[5];
    const float* bv = (const float*)d_in[6];
    const float* Wo = (const float*)d_in[7];
    const float* bo = (const float*)d_in[8];

    float* out = (float*)d_out;
    const size_t OUT_ELEMS   = (size_t)S_LEN * HID;
    const size_t PROBS_ELEMS = (size_t)NH * S_LEN * WIN;
    float* probs = out + OUT_ELEMS;
    int write_probs = ((size_t)out_size >= OUT_ELEMS + PROBS_ELEMS) ? 1 : 0;

    cudaFuncSetAttribute(attn_kernel,
                         cudaFuncAttributeMaxDynamicSharedMemorySize, ASMEM);
    cudaFuncSetAttribute(hgemm,
                         cudaFuncAttributeMaxDynamicSharedMemorySize, 2 * BUFB);

    conv_act<<<(S_LEN * HID) / 1024, 256>>>(X, 0);
    dim3 ct(32, 8), cg(HID / 32, HID / 32);
    conv_w_t<<<cg, ct>>>(Wq, 0);
    conv_w_t<<<cg, ct>>>(Wk, HID * HID);
    conv_w_t<<<cg, ct>>>(Wv, 2 * HID * HID);
    conv_w_t<<<cg, ct>>>(Wo, 3 * HID * HID);

    dim3 ggrid(GN / 128, S_LEN / 128);
    hgemm<<<ggrid, 256, 2 * BUFB>>>(0,             bq, nullptr, 1);
    hgemm<<<ggrid, 256, 2 * BUFB>>>(HID * HID,     bk, nullptr, 2);
    hgemm<<<ggrid, 256, 2 * BUFB>>>(2 * HID * HID, bv, nullptr, 3);

    dim3 agrid(S_LEN / QT, NH);
    attn_kernel<<<agrid, 256, ASMEM>>>(probs, write_probs);

    conv_act<<<(S_LEN * HID) / 1024, 256>>>(nullptr, 4);
    hgemm<<<ggrid, 256, 2 * BUFB>>>(3 * HID * HID, bo, out, 0);
}

// round 10
// speedup vs baseline: 2.5084x; 1.0168x over previous
#include <cuda_runtime.h>
#include <cuda_bf16.h>
#include <cstdint>

#define S_LEN 4096
#define HID   1024
#define NH    16
#define HD    64
#define WIN   512
#define HALF  256
#define QT    32
#define GK    1024
#define GN    1024

// ---- scratch (no cudaMalloc allowed); referenced only from device code ----
__device__ float g_q[S_LEN * HID];
__device__ float g_k[S_LEN * HID];
__device__ float g_v[S_LEN * HID];
__device__ float g_ctx[S_LEN * HID];
__device__ __nv_bfloat16 g_xh[S_LEN * HID];
__device__ __nv_bfloat16 g_xl[S_LEN * HID];
__device__ __nv_bfloat16 g_wth[4 * HID * HID];
__device__ __nv_bfloat16 g_wtl[4 * HID * HID];

__device__ __forceinline__ uint32_t smem_u32(const void* p) {
    uint32_t a;
    asm("{ .reg .u64 t; cvta.to.shared.u64 t, %1; cvt.u32.u64 %0, t; }"
        : "=r"(a) : "l"(p));
    return a;
}

#define CP16(dst, src) \
    asm volatile("cp.async.cg.shared.global [%0], [%1], 16;" \
                 :: "r"(dst), "l"(src) : "memory")
#define CP_COMMIT() asm volatile("cp.async.commit_group;" ::: "memory")
#define CP_WAIT1()  asm volatile("cp.async.wait_group 1;" ::: "memory")
#define CP_WAIT0()  asm volatile("cp.async.wait_group 0;" ::: "memory")

#define LDSM4(r, a) \
    asm volatile("ldmatrix.sync.aligned.m8n8.x4.shared.b16 {%0,%1,%2,%3}, [%4];" \
                 : "=r"((r)[0]), "=r"((r)[1]), "=r"((r)[2]), "=r"((r)[3]) \
                 : "r"(a))

#define MMA16816(d, a, b0, b1) \
    asm volatile("mma.sync.aligned.m16n8k16.row.col.f32.bf16.bf16.f32 " \
                 "{%0,%1,%2,%3}, {%4,%5,%6,%7}, {%8,%9}, {%0,%1,%2,%3};" \
                 : "+f"((d)[0]), "+f"((d)[1]), "+f"((d)[2]), "+f"((d)[3]) \
                 : "r"((a)[0]), "r"((a)[1]), "r"((a)[2]), "r"((a)[3]), \
                   "r"(b0), "r"(b1))

__device__ __forceinline__ void split_bf16(float v, __nv_bfloat16& h,
                                           __nv_bfloat16& l) {
    h = __float2bfloat16(v);
    l = __float2bfloat16(v - __bfloat162float(h));
}
__device__ __forceinline__ uint32_t pk2(__nv_bfloat16 a, __nv_bfloat16 b) {
    return ((uint32_t)__bfloat16_as_ushort(b) << 16) | __bfloat16_as_ushort(a);
}
__device__ __forceinline__ void sp2(float a, float b, uint32_t& hp, uint32_t& lp) {
    __nv_bfloat16 ha, la, hb, lb;
    split_bf16(a, ha, la);
    split_bf16(b, hb, lb);
    hp = pk2(ha, hb);
    lp = pk2(la, lb);
}

// ============================================================================
// convert activations (X or g_ctx) -> g_xh/g_xl
// ============================================================================
__global__ __launch_bounds__(256)
void conv_act(const float* __restrict__ src_ext, int tag)
{
    const float* src = (tag == 4) ? g_ctx : src_ext;
    size_t i = (size_t)blockIdx.x * 256 + threadIdx.x;
    float4 v = *(const float4*)(src + i * 4);
    uint2 hp, lp;
    sp2(v.x, v.y, hp.x, lp.x);
    sp2(v.z, v.w, hp.y, lp.y);
    *(uint2*)&g_xh[i * 4] = hp;
    *(uint2*)&g_xl[i * 4] = lp;
}

// ============================================================================
// convert + transpose weight W[K,N] -> g_wth/g_wtl[N,K] at offset woff
// ============================================================================
__global__ __launch_bounds__(256)
void conv_w_t(const float* __restrict__ W, int woff)
{
    __shared__ float tile[32][33];
    const int tx = threadIdx.x, ty = threadIdx.y;
#pragma unroll
    for (int j = 0; j < 4; j++)
        tile[ty + 8 * j][tx] =
            W[(size_t)(blockIdx.y * 32 + ty + 8 * j) * HID + blockIdx.x * 32 + tx];
    __syncthreads();
#pragma unroll
    for (int j = 0; j < 4; j++) {
        float v = tile[tx][ty + 8 * j];
        __nv_bfloat16 h, l;
        split_bf16(v, h, l);
        size_t o = (size_t)woff +
                   (size_t)(blockIdx.x * 32 + ty + 8 * j) * HID + blockIdx.y * 32 + tx;
        g_wth[o] = h;
        g_wtl[o] = l;
    }
}

// ============================================================================
// Big-tile HMMA split-bf16 GEMM body.
// Block tile 256m x 128n, BK=32, warps 4m x 2n, warp tile 64x64.
// smem per buffer (AST=40 halves = 80 B rows, conflict-free, validated):
//   Ah: rows 0..255   @ 0        (row*80)
//   Al: rows 0..255   @ 20480
//   Bh: rows 0..127   @ 40960
//   Bl: rows 0..127   @ 51200
// buffer = 61440 B, double buffered = 122880 B -> 1 CTA/SM.
// ============================================================================
#define AST   40
#define GBUFB 61440
#define GSMEM (2 * GBUFB)

__device__ __forceinline__ void hgemm_body(
    int woff, const float* __restrict__ bias, float* __restrict__ C,
    int m0, int n0)
{
    extern __shared__ __align__(128) char hsm[];
    const int t = threadIdx.x, wid = t >> 5, lane = t & 31;
    const uint32_t sb = smem_u32(hsm);

    // ---- staging map: 6 reps x (2 CP16) per chunk ----
    const int lrow = t >> 1;                 // 0..127
    const int segH = (t & 1) * 16;           // halves
    const __nv_bfloat16* gsrc[6];
    uint32_t sdst[6];
    gsrc[0] = g_xh + (size_t)(m0 + lrow) * GK + segH;
    sdst[0] = (uint32_t)(lrow * 80) + segH * 2;
    gsrc[1] = g_xh + (size_t)(m0 + 128 + lrow) * GK + segH;
    sdst[1] = (uint32_t)((128 + lrow) * 80) + segH * 2;
    gsrc[2] = g_xl + (size_t)(m0 + lrow) * GK + segH;
    sdst[2] = 20480u + (uint32_t)(lrow * 80) + segH * 2;
    gsrc[3] = g_xl + (size_t)(m0 + 128 + lrow) * GK + segH;
    sdst[3] = 20480u + (uint32_t)((128 + lrow) * 80) + segH * 2;
    gsrc[4] = g_wth + woff + (size_t)(n0 + lrow) * GK + segH;
    sdst[4] = 40960u + (uint32_t)(lrow * 80) + segH * 2;
    gsrc[5] = g_wtl + woff + (size_t)(n0 + lrow) * GK + segH;
    sdst[5] = 51200u + (uint32_t)(lrow * 80) + segH * 2;

    const int warp_m = wid & 3, warp_n = wid >> 2;
    const int l16 = lane & 15, lh8 = (lane >> 4) * 8;

    float acc[4][8][4];
#pragma unroll
    for (int i = 0; i < 4; i++)
#pragma unroll
        for (int j = 0; j < 8; j++)
#pragma unroll
            for (int e = 0; e < 4; e++) acc[i][j][e] = 0.f;

#define GISSUE(c) do {                                                       \
    const uint32_t bo_ = sb + ((c) & 1) * GBUFB;                             \
    const int ko_ = (c) * 32;                                                \
    _Pragma("unroll")                                                        \
    for (int r_ = 0; r_ < 6; r_++) {                                         \
        CP16(bo_ + sdst[r_],      gsrc[r_] + ko_);                           \
        CP16(bo_ + sdst[r_] + 16, gsrc[r_] + ko_ + 8);                       \
    }                                                                        \
    CP_COMMIT();                                                             \
} while (0)

    GISSUE(0);
    for (int c = 0; c < 32; c++) {
        if (c + 1 < 32) { GISSUE(c + 1); CP_WAIT1(); }
        else            { CP_WAIT0(); }
        __syncthreads();

        const uint32_t ab = sb + (c & 1) * GBUFB;
#pragma unroll
        for (int ks = 0; ks < 32; ks += 16) {
            uint32_t ah[4][4], al[4][4];
#pragma unroll
            for (int mf = 0; mf < 4; mf++) {
                uint32_t ad = ab +
                    (uint32_t)((warp_m * 64 + mf * 16 + l16) * AST + ks + lh8) * 2;
                LDSM4(ah[mf], ad);
                LDSM4(al[mf], ad + 20480);
            }
#pragma unroll
            for (int nf = 0; nf < 4; nf++) {
                uint32_t bh[4], bl[4];
                uint32_t bd = ab + 40960u +
                    (uint32_t)((warp_n * 64 + nf * 16 + l16) * AST + ks + lh8) * 2;
                LDSM4(bh, bd);
                LDSM4(bl, bd + 10240);
#pragma unroll
                for (int mf = 0; mf < 4; mf++)
#pragma unroll
                    for (int j = 0; j < 2; j++) {
                        float* d = acc[mf][nf * 2 + j];
                        MMA16816(d, ah[mf], bh[j], bh[j + 2]);
                        MMA16816(d, ah[mf], bl[j], bl[j + 2]);
                        MMA16816(d, al[mf], bh[j], bh[j + 2]);
                    }
            }
        }
        __syncthreads();
    }

    // ---- epilogue ----
    const int er = lane >> 2, ec = (lane & 3) * 2;
#pragma unroll
    for (int mf = 0; mf < 4; mf++)
#pragma unroll
        for (int n8 = 0; n8 < 8; n8++) {
            int m = m0 + warp_m * 64 + mf * 16 + er;
            int n = n0 + warp_n * 64 + n8 * 8 + ec;
            float bx = bias[n], by = bias[n + 1];
            float* a4 = acc[mf][n8];
            *(float2*)&C[(size_t)m * GN + n] =
                make_float2(a4[0] + bx, a4[1] + by);
            *(float2*)&C[(size_t)(m + 8) * GN + n] =
                make_float2(a4[2] + bx, a4[3] + by);
        }
#undef GISSUE
}

// fused Q/K/V projection: grid (24, 16); blockIdx.x>>3 selects the weight
__global__ __launch_bounds__(256, 1)
void hgemm_qkv(const float* __restrict__ bq, const float* __restrict__ bk,
               const float* __restrict__ bv)
{
    const int which = blockIdx.x >> 3;
    const int n0 = (blockIdx.x & 7) * 128;
    const int m0 = blockIdx.y * 256;
    float* C = (which == 0) ? g_q : (which == 1) ? g_k : g_v;
    const float* bias = (which == 0) ? bq : (which == 1) ? bk : bv;
    hgemm_body(which * HID * HID, bias, C, m0, n0);
}

// output projection: grid (8, 16)
__global__ __launch_bounds__(256, 1)
void hgemm_o(const float* __restrict__ bo, float* __restrict__ out)
{
    hgemm_body(3 * HID * HID, bo, out, blockIdx.y * 256, blockIdx.x * 128);
}

// ============================================================================
// HMMA sliding-window attention (unchanged from the 762us passing version)
// ============================================================================
#define PSTH  552
#define KSTH  72
#define APHB  0
#define APLB  35328
#define AKVB  70656
#define AQHB  89088
#define AQLB  93696
#define APRT  98304
#define ASNV  99328
#define ASMEM 99456

__global__ __launch_bounds__(256, 2)
void attn_kernel(float* __restrict__ probs, int write_probs)
{
    extern __shared__ __align__(128) char am[];
    const uint32_t sb = smem_u32(am);

    const int t    = threadIdx.x;
    const int lane = t & 31;
    const int w    = t >> 5;
    const int q0   = blockIdx.x * QT;
    const int h    = blockIdx.y;
    const int hoff = h * HD;
    const int kmin = q0 - HALF;

    float* part = (float*)(am + APRT);
    float* sinv = (float*)(am + ASNV);
    part[t] = 0.f;

    if (t < 128) {
        int row = t >> 2, dg = (t & 3) * 16;
        const float4* s4 = (const float4*)&g_q[(size_t)(q0 + row) * HID + hoff + dg];
        uint32_t hp[8], lp[8];
#pragma unroll
        for (int u = 0; u < 4; u++) {
            float4 v = s4[u];
            sp2(v.x, v.y, hp[u * 2], lp[u * 2]);
            sp2(v.z, v.w, hp[u * 2 + 1], lp[u * 2 + 1]);
        }
        uint32_t o = (uint32_t)(row * KSTH + dg) * 2;
        *(uint4*)(am + AQHB + o)      = make_uint4(hp[0], hp[1], hp[2], hp[3]);
        *(uint4*)(am + AQHB + o + 16) = make_uint4(hp[4], hp[5], hp[6], hp[7]);
        *(uint4*)(am + AQLB + o)      = make_uint4(lp[0], lp[1], lp[2], lp[3]);
        *(uint4*)(am + AQLB + o + 16) = make_uint4(lp[4], lp[5], lp[6], lp[7]);
    }
    __syncthreads();

    const int mt  = w & 1;
    const int nb  = (w >> 1) * 16;
    const int ds  = w >> 1;
    const int l16 = lane & 15, lh8 = (lane >> 4) * 8;

    uint32_t qh[4][4], ql[4][4];
#pragma unroll
    for (int ks = 0; ks < 4; ks++) {
        uint32_t ad = sb + AQHB + (uint32_t)((mt * 16 + l16) * KSTH + ks * 16 + lh8) * 2;
        LDSM4(qh[ks], ad);
        LDSM4(ql[ks], ad + (AQLB - AQHB));
    }

    float rs0 = 0.f, rs1 = 0.f;
    const int r0 = mt * 16 + (lane >> 2), r1 = r0 + 8;

    for (int cc = 0; cc < 9; cc++) {
        const int cb = cc * 64;
        const int W  = (cc == 8) ? 32 : 64;
        __syncthreads();
        {
            int row = t >> 2, dg = (t & 3) * 16;
            if (row < W) {
                int key = kmin + cb + row;
                bool ok = (key >= 0 && key < S_LEN);
                uint32_t hp[8], lp[8];
                if (ok) {
                    const float4* s4 =
                        (const float4*)&g_k[(size_t)key * HID + hoff + dg];
#pragma unroll
                    for (int u = 0; u < 4; u++) {
                        float4 v = s4[u];
                        sp2(v.x, v.y, hp[u * 2], lp[u * 2]);
                        sp2(v.z, v.w, hp[u * 2 + 1], lp[u * 2 + 1]);
                    }
                } else {
#pragma unroll
                    for (int u = 0; u < 8; u++) { hp[u] = 0; lp[u] = 0; }
                }
                uint32_t o = (uint32_t)(row * KSTH + dg) * 2;
                *(uint4*)(am + AKVB + o)      = make_uint4(hp[0], hp[1], hp[2], hp[3]);
                *(uint4*)(am + AKVB + o + 16) = make_uint4(hp[4], hp[5], hp[6], hp[7]);
                *(uint4*)(am + AKVB + 9216 + o)      = make_uint4(lp[0], lp[1], lp[2], lp[3]);
                *(uint4*)(am + AKVB + 9216 + o + 16) = make_uint4(lp[4], lp[5], lp[6], lp[7]);
            }
        }
        __syncthreads();

        if (nb < W) {
            float acc[2][4];
#pragma unroll
            for (int j = 0; j < 2; j++)
#pragma unroll
                for (int e = 0; e < 4; e++) acc[j][e] = 0.f;

#pragma unroll
            for (int ks = 0; ks < 4; ks++) {
                uint32_t bh[4], bl[4];
                uint32_t bd = sb + AKVB +
                    (uint32_t)((nb + l16) * KSTH + ks * 16 + lh8) * 2;
                LDSM4(bh, bd);
                LDSM4(bl, bd + 9216);
#pragma unroll
                for (int j = 0; j < 2; j++) {
                    MMA16816(acc[j], qh[ks], bh[j], bh[j + 2]);
                    MMA16816(acc[j], qh[ks], bl[j], bl[j + 2]);
                    MMA16816(acc[j], ql[ks], bh[j], bh[j + 2]);
                }
            }
#pragma unroll
            for (int j = 0; j < 2; j++) {
                int c0 = cb + nb + j * 8 + (lane & 3) * 2;
                float o00 = ((unsigned)(c0 - r0) < WIN)
                            ? __expf(acc[j][0] * 0.125f) : 0.f;
                float o01 = ((unsigned)(c0 + 1 - r0) < WIN)
                            ? __expf(acc[j][1] * 0.125f) : 0.f;
                float o10 = ((unsigned)(c0 - r1) < WIN)
                            ? __expf(acc[j][2] * 0.125f) : 0.f;
                float o11 = ((unsigned)(c0 + 1 - r1) < WIN)
                            ? __expf(acc[j][3] * 0.125f) : 0.f;
                rs0 += o00 + o01;
                rs1 += o10 + o11;
                uint32_t hp, lp;
                sp2(o00, o01, hp, lp);
                *(uint32_t*)(am + APHB + (uint32_t)(r0 * PSTH + c0) * 2) = hp;
                *(uint32_t*)(am + APLB + (uint32_t)(r0 * PSTH + c0) * 2) = lp;
                sp2(o10, o11, hp, lp);
                *(uint32_t*)(am + APHB + (uint32_t)(r1 * PSTH + c0) * 2) = hp;
                *(uint32_t*)(am + APLB + (uint32_t)(r1 * PSTH + c0) * 2) = lp;
            }
        }
    }

    rs0 += __shfl_xor_sync(0xFFFFFFFFu, rs0, 1);
    rs0 += __shfl_xor_sync(0xFFFFFFFFu, rs0, 2);
    rs1 += __shfl_xor_sync(0xFFFFFFFFu, rs1, 1);
    rs1 += __shfl_xor_sync(0xFFFFFFFFu, rs1, 2);
    if ((lane & 3) == 0) {
        part[w * 32 + r0] = rs0;
        part[w * 32 + r1] = rs1;
    }
    __syncthreads();
    if (t < 32) {
        float s = 0.f;
#pragma unroll
        for (int w8 = 0; w8 < 8; w8++) s += part[w8 * 32 + t];
        sinv[t] = 1.f / s;
    }
    __syncthreads();

    if (write_probs) {
        float* pr = probs + ((size_t)h * S_LEN + q0) * WIN;
        for (int idx = t; idx < QT * WIN; idx += 256) {
            int qi = idx >> 9, ww = idx & (WIN - 1);
            uint32_t o = (uint32_t)(qi * PSTH + qi + ww) * 2;
            float ph = __bfloat162float(*(__nv_bfloat16*)(am + APHB + o));
            float pl = __bfloat162float(*(__nv_bfloat16*)(am + APLB + o));
            pr[(size_t)qi * WIN + ww] = (ph + pl) * sinv[qi];
        }
    }

    float acc2[2][4];
#pragma unroll
    for (int j = 0; j < 2; j++)
#pragma unroll
        for (int e = 0; e < 4; e++) acc2[j][e] = 0.f;

    for (int cc = 0; cc < 9; cc++) {
        const int cb = cc * 64;
        const int W  = (cc == 8) ? 32 : 64;
        __syncthreads();
        {
            int keyl = t >> 2, dg = (t & 3) * 16;
            if (keyl < W) {
                int key = kmin + cb + keyl;
                bool ok = (key >= 0 && key < S_LEN);
                const float4* s4 =
                    (const float4*)&g_v[(size_t)key * HID + hoff + dg];
#pragma unroll
                for (int u = 0; u < 4; u++) {
                    float4 v = ok ? s4[u] : make_float4(0.f, 0.f, 0.f, 0.f);
                    float vv[4] = {v.x, v.y, v.z, v.w};
#pragma unroll
                    for (int e = 0; e < 4; e++) {
                        __nv_bfloat16 hh, ll;
                        split_bf16(vv[e], hh, ll);
                        int d = dg + u * 4 + e;
                        uint32_t o = (uint32_t)(d * KSTH + keyl) * 2;
                        *(__nv_bfloat16*)(am + AKVB + o)        = hh;
                        *(__nv_bfloat16*)(am + AKVB + 9216 + o) = ll;
                    }
                }
            }
        }
        __syncthreads();

        const int nks = W >> 4;
        for (int ks = 0; ks < nks; ks++) {
            uint32_t pah[4], pal[4], vbh[4], vbl[4];
            uint32_t pd = sb + APHB +
                (uint32_t)((mt * 16 + l16) * PSTH + cb + ks * 16 + lh8) * 2;
            LDSM4(pah, pd);
            LDSM4(pal, pd + (APLB - APHB));
            uint32_t vd = sb + AKVB +
                (uint32_t)((ds * 16 + l16) * KSTH + ks * 16 + lh8) * 2;
            LDSM4(vbh, vd);
            LDSM4(vbl, vd + 9216);
#pragma unroll
            for (int j = 0; j < 2; j++) {
                MMA16816(acc2[j], pah, vbh[j], vbh[j + 2]);
                MMA16816(acc2[j], pah, vbl[j], vbl[j + 2]);
                MMA16816(acc2[j], pal, vbh[j], vbh[j + 2]);
            }
        }
    }

    {
        float i0 = sinv[r0], i1 = sinv[r1];
#pragma unroll
        for (int j = 0; j < 2; j++) {
            int c = ds * 16 + j * 8 + (lane & 3) * 2;
            *(float2*)&g_ctx[(size_t)(q0 + r0) * HID + hoff + c] =
                make_float2(acc2[j][0] * i0, acc2[j][1] * i0);
            *(float2*)&g_ctx[(size_t)(q0 + r1) * HID + hoff + c] =
                make_float2(acc2[j][2] * i1, acc2[j][3] * i1);
        }
    }
}

// ============================================================================
extern "C" void kernel_launch(void* const* d_in, const int* in_sizes, int n_in,
                              void* d_out, int out_size)
{
    const float* X  = (const float*)d_in[0];
    const float* Wq = (const float*)d_in[1];
    const float* bq = (const float*)d_in[2];
    const float* Wk = (const float*)d_in[3];
    const float* bk = (const float*)d_in[4];
    const float* Wv = (const float*)d_in[5];
    const float* bv = (const float*)d_in[6];
    const float* Wo = (const float*)d_in[7];
    const float* bo = (const float*)d_in[8];

    float* out = (float*)d_out;
    const size_t OUT_ELEMS   = (size_t)S_LEN * HID;
    const size_t PROBS_ELEMS = (size_t)NH * S_LEN * WIN;
    float* probs = out + OUT_ELEMS;
    int write_probs = ((size_t)out_size >= OUT_ELEMS + PROBS_ELEMS) ? 1 : 0;

    cudaFuncSetAttribute(attn_kernel,
                         cudaFuncAttributeMaxDynamicSharedMemorySize, ASMEM);
    cudaFuncSetAttribute(hgemm_qkv,
                         cudaFuncAttributeMaxDynamicSharedMemorySize, GSMEM);
    cudaFuncSetAttribute(hgemm_o,
                         cudaFuncAttributeMaxDynamicSharedMemorySize, GSMEM);

    conv_act<<<(S_LEN * HID) / 1024, 256>>>(X, 0);
    dim3 ct(32, 8), cg(HID / 32, HID / 32);
    conv_w_t<<<cg, ct>>>(Wq, 0);
    conv_w_t<<<cg, ct>>>(Wk, HID * HID);
    conv_w_t<<<cg, ct>>>(Wv, 2 * HID * HID);
    conv_w_t<<<cg, ct>>>(Wo, 3 * HID * HID);

    hgemm_qkv<<<dim3(24, 16), 256, GSMEM>>>(bq, bk, bv);

    dim3 agrid(S_LEN / QT, NH);
    attn_kernel<<<agrid, 256, ASMEM>>>(probs, write_probs);

    conv_act<<<(S_LEN * HID) / 1024, 256>>>(nullptr, 4);
    hgemm_o<<<dim3(8, 16), 256, GSMEM>>>(bo, out);
}

// round 12
// speedup vs baseline: 2.6458x; 1.0548x over previous
#include <cuda_runtime.h>
#include <cuda_bf16.h>
#include <cstdint>

#define S_LEN 4096
#define HID   1024
#define NH    16
#define HD    64
#define WIN   512
#define HALF  256
#define QT    32
#define GK    1024
#define GN    1024

// ---- scratch (no cudaMalloc allowed); referenced only from device code ----
__device__ __nv_bfloat16 g_xh[S_LEN * HID];   // X split (later: ctx split)
__device__ __nv_bfloat16 g_xl[S_LEN * HID];
__device__ __nv_bfloat16 g_wth[4 * HID * HID];
__device__ __nv_bfloat16 g_wtl[4 * HID * HID];
__device__ __nv_bfloat16 g_qh[S_LEN * HID];
__device__ __nv_bfloat16 g_ql[S_LEN * HID];
__device__ __nv_bfloat16 g_kh[S_LEN * HID];
__device__ __nv_bfloat16 g_kl[S_LEN * HID];
__device__ __nv_bfloat16 g_vh[S_LEN * HID];
__device__ __nv_bfloat16 g_vl[S_LEN * HID];

__device__ __forceinline__ uint32_t smem_u32(const void* p) {
    uint32_t a;
    asm("{ .reg .u64 t; cvta.to.shared.u64 t, %1; cvt.u32.u64 %0, t; }"
        : "=r"(a) : "l"(p));
    return a;
}

#define CP16(dst, src) \
    asm volatile("cp.async.cg.shared.global [%0], [%1], 16;" \
                 :: "r"(dst), "l"(src) : "memory")
#define CP16Z(dst, src, sz) \
    asm volatile("cp.async.cg.shared.global [%0], [%1], 16, %2;" \
                 :: "r"(dst), "l"(src), "r"(sz) : "memory")
#define CP_COMMIT() asm volatile("cp.async.commit_group;" ::: "memory")
#define CP_WAIT1()  asm volatile("cp.async.wait_group 1;" ::: "memory")
#define CP_WAIT0()  asm volatile("cp.async.wait_group 0;" ::: "memory")

#define LDSM4(r, a) \
    asm volatile("ldmatrix.sync.aligned.m8n8.x4.shared.b16 {%0,%1,%2,%3}, [%4];" \
                 : "=r"((r)[0]), "=r"((r)[1]), "=r"((r)[2]), "=r"((r)[3]) \
                 : "r"(a))

#define MMA16816(d, a, b0, b1) \
    asm volatile("mma.sync.aligned.m16n8k16.row.col.f32.bf16.bf16.f32 " \
                 "{%0,%1,%2,%3}, {%4,%5,%6,%7}, {%8,%9}, {%0,%1,%2,%3};" \
                 : "+f"((d)[0]), "+f"((d)[1]), "+f"((d)[2]), "+f"((d)[3]) \
                 : "r"((a)[0]), "r"((a)[1]), "r"((a)[2]), "r"((a)[3]), \
                   "r"(b0), "r"(b1))

__device__ __forceinline__ void split_bf16(float v, __nv_bfloat16& h,
                                           __nv_bfloat16& l) {
    h = __float2bfloat16(v);
    l = __float2bfloat16(v - __bfloat162float(h));
}
__device__ __forceinline__ uint32_t pk2(__nv_bfloat16 a, __nv_bfloat16 b) {
    return ((uint32_t)__bfloat16_as_ushort(b) << 16) | __bfloat16_as_ushort(a);
}
__device__ __forceinline__ void sp2(float a, float b, uint32_t& hp, uint32_t& lp) {
    __nv_bfloat16 ha, la, hb, lb;
    split_bf16(a, ha, la);
    split_bf16(b, hb, lb);
    hp = pk2(ha, hb);
    lp = pk2(la, lb);
}

// ============================================================================
// convert X -> g_xh/g_xl
// ============================================================================
__global__ __launch_bounds__(256)
void conv_act(const float* __restrict__ src)
{
    size_t i = (size_t)blockIdx.x * 256 + threadIdx.x;
    float4 v = *(const float4*)(src + i * 4);
    uint2 hp, lp;
    sp2(v.x, v.y, hp.x, lp.x);
    sp2(v.z, v.w, hp.y, lp.y);
    *(uint2*)&g_xh[i * 4] = hp;
    *(uint2*)&g_xl[i * 4] = lp;
}

// ============================================================================
// convert + transpose weight W[K,N] -> g_wth/g_wtl[N,K] at offset woff
// ============================================================================
__global__ __launch_bounds__(256)
void conv_w_t(const float* __restrict__ W, int woff)
{
    __shared__ float tile[32][33];
    const int tx = threadIdx.x, ty = threadIdx.y;
#pragma unroll
    for (int j = 0; j < 4; j++)
        tile[ty + 8 * j][tx] =
            W[(size_t)(blockIdx.y * 32 + ty + 8 * j) * HID + blockIdx.x * 32 + tx];
    __syncthreads();
#pragma unroll
    for (int j = 0; j < 4; j++) {
        float v = tile[tx][ty + 8 * j];
        __nv_bfloat16 h, l;
        split_bf16(v, h, l);
        size_t o = (size_t)woff +
                   (size_t)(blockIdx.x * 32 + ty + 8 * j) * HID + blockIdx.y * 32 + tx;
        g_wth[o] = h;
        g_wtl[o] = l;
    }
}

// ============================================================================
// Big-tile HMMA split-bf16 GEMM body (mainloop identical to 749.6us version).
// Epilogue mode: Cf != nullptr -> fp32 out; else split-bf16 into Ch/Cl.
// ============================================================================
#define AST   40
#define GBUFB 61440
#define GSMEM (2 * GBUFB)

__device__ __forceinline__ void hgemm_body(
    int woff, const float* __restrict__ bias,
    float* __restrict__ Cf,
    __nv_bfloat16* __restrict__ Ch, __nv_bfloat16* __restrict__ Cl,
    int m0, int n0)
{
    extern __shared__ __align__(128) char hsm[];
    const int t = threadIdx.x, wid = t >> 5, lane = t & 31;
    const uint32_t sb = smem_u32(hsm);

    const int lrow = t >> 1;
    const int segH = (t & 1) * 16;
    const __nv_bfloat16* gsrc[6];
    uint32_t sdst[6];
    gsrc[0] = g_xh + (size_t)(m0 + lrow) * GK + segH;
    sdst[0] = (uint32_t)(lrow * 80) + segH * 2;
    gsrc[1] = g_xh + (size_t)(m0 + 128 + lrow) * GK + segH;
    sdst[1] = (uint32_t)((128 + lrow) * 80) + segH * 2;
    gsrc[2] = g_xl + (size_t)(m0 + lrow) * GK + segH;
    sdst[2] = 20480u + (uint32_t)(lrow * 80) + segH * 2;
    gsrc[3] = g_xl + (size_t)(m0 + 128 + lrow) * GK + segH;
    sdst[3] = 20480u + (uint32_t)((128 + lrow) * 80) + segH * 2;
    gsrc[4] = g_wth + woff + (size_t)(n0 + lrow) * GK + segH;
    sdst[4] = 40960u + (uint32_t)(lrow * 80) + segH * 2;
    gsrc[5] = g_wtl + woff + (size_t)(n0 + lrow) * GK + segH;
    sdst[5] = 51200u + (uint32_t)(lrow * 80) + segH * 2;

    const int warp_m = wid & 3, warp_n = wid >> 2;
    const int l16 = lane & 15, lh8 = (lane >> 4) * 8;

    float acc[4][8][4];
#pragma unroll
    for (int i = 0; i < 4; i++)
#pragma unroll
        for (int j = 0; j < 8; j++)
#pragma unroll
            for (int e = 0; e < 4; e++) acc[i][j][e] = 0.f;

#define GISSUE(c) do {                                                       \
    const uint32_t bo_ = sb + ((c) & 1) * GBUFB;                             \
    const int ko_ = (c) * 32;                                                \
    _Pragma("unroll")                                                        \
    for (int r_ = 0; r_ < 6; r_++) {                                         \
        CP16(bo_ + sdst[r_],      gsrc[r_] + ko_);                           \
        CP16(bo_ + sdst[r_] + 16, gsrc[r_] + ko_ + 8);                       \
    }                                                                        \
    CP_COMMIT();                                                             \
} while (0)

    GISSUE(0);
    for (int c = 0; c < 32; c++) {
        if (c + 1 < 32) { GISSUE(c + 1); CP_WAIT1(); }
        else            { CP_WAIT0(); }
        __syncthreads();

        const uint32_t ab = sb + (c & 1) * GBUFB;
#pragma unroll
        for (int ks = 0; ks < 32; ks += 16) {
            uint32_t ah[4][4], al[4][4];
#pragma unroll
            for (int mf = 0; mf < 4; mf++) {
                uint32_t ad = ab +
                    (uint32_t)((warp_m * 64 + mf * 16 + l16) * AST + ks + lh8) * 2;
                LDSM4(ah[mf], ad);
                LDSM4(al[mf], ad + 20480);
            }
#pragma unroll
            for (int nf = 0; nf < 4; nf++) {
                uint32_t bh[4], bl[4];
                uint32_t bd = ab + 40960u +
                    (uint32_t)((warp_n * 64 + nf * 16 + l16) * AST + ks + lh8) * 2;
                LDSM4(bh, bd);
                LDSM4(bl, bd + 10240);
#pragma unroll
                for (int mf = 0; mf < 4; mf++)
#pragma unroll
                    for (int j = 0; j < 2; j++) {
                        float* d = acc[mf][nf * 2 + j];
                        MMA16816(d, ah[mf], bh[j], bh[j + 2]);
                        MMA16816(d, ah[mf], bl[j], bl[j + 2]);
                        MMA16816(d, al[mf], bh[j], bh[j + 2]);
                    }
            }
        }
        __syncthreads();
    }

    const int er = lane >> 2, ec = (lane & 3) * 2;
#pragma unroll
    for (int mf = 0; mf < 4; mf++)
#pragma unroll
        for (int n8 = 0; n8 < 8; n8++) {
            int m = m0 + warp_m * 64 + mf * 16 + er;
            int n = n0 + warp_n * 64 + n8 * 8 + ec;
            float bx = bias[n], by = bias[n + 1];
            float* a4 = acc[mf][n8];
            if (Cf) {
                *(float2*)&Cf[(size_t)m * GN + n] =
                    make_float2(a4[0] + bx, a4[1] + by);
                *(float2*)&Cf[(size_t)(m + 8) * GN + n] =
                    make_float2(a4[2] + bx, a4[3] + by);
            } else {
                uint32_t hp, lp;
                sp2(a4[0] + bx, a4[1] + by, hp, lp);
                *(uint32_t*)&Ch[(size_t)m * GN + n] = hp;
                *(uint32_t*)&Cl[(size_t)m * GN + n] = lp;
                sp2(a4[2] + bx, a4[3] + by, hp, lp);
                *(uint32_t*)&Ch[(size_t)(m + 8) * GN + n] = hp;
                *(uint32_t*)&Cl[(size_t)(m + 8) * GN + n] = lp;
            }
        }
#undef GISSUE
}

// fused Q/K/V projection -> split bf16 outputs
__global__ __launch_bounds__(256, 1)
void hgemm_qkv(const float* __restrict__ bq, const float* __restrict__ bk,
               const float* __restrict__ bv)
{
    const int which = blockIdx.x >> 3;
    const int n0 = (blockIdx.x & 7) * 128;
    const int m0 = blockIdx.y * 256;
    __nv_bfloat16 *Ch, *Cl;
    const float* bias;
    if (which == 0)      { Ch = g_qh; Cl = g_ql; bias = bq; }
    else if (which == 1) { Ch = g_kh; Cl = g_kl; bias = bk; }
    else                 { Ch = g_vh; Cl = g_vl; bias = bv; }
    hgemm_body(which * HID * HID, bias, nullptr, Ch, Cl, m0, n0);
}

// output projection (fp32 out)
__global__ __launch_bounds__(256, 1)
void hgemm_o(const float* __restrict__ bo, float* __restrict__ out)
{
    hgemm_body(3 * HID * HID, bo, out, nullptr, nullptr,
               blockIdx.y * 256, blockIdx.x * 128);
}

// ============================================================================
// HMMA sliding-window attention; staging now from pre-split bf16 via cp.async.
// ctx epilogue writes split bf16 directly into g_xh/g_xl (A of hgemm_o).
// ============================================================================
#define PSTH  552
#define KSTH  72
#define APHB  0
#define APLB  35328
#define AKVB  70656
#define AQHB  89088
#define AQLB  93696
#define APRT  98304
#define ASNV  99328
#define ASMEM 99456

__global__ __launch_bounds__(256, 2)
void attn_kernel(float* __restrict__ probs, int write_probs)
{
    extern __shared__ __align__(128) char am[];
    const uint32_t sb = smem_u32(am);

    const int t    = threadIdx.x;
    const int lane = t & 31;
    const int w    = t >> 5;
    const int q0   = blockIdx.x * QT;
    const int h    = blockIdx.y;
    const int hoff = h * HD;
    const int kmin = q0 - HALF;

    float* part = (float*)(am + APRT);
    float* sinv = (float*)(am + ASNV);
    part[t] = 0.f;

    // ---- stage Q (pre-split) via cp.async ----
    if (t < 128) {
        int row = t >> 2, dg = (t & 3) * 16;
        const __nv_bfloat16* sh = g_qh + (size_t)(q0 + row) * HID + hoff + dg;
        const __nv_bfloat16* sl = g_ql + (size_t)(q0 + row) * HID + hoff + dg;
        uint32_t o = sb + (uint32_t)(row * KSTH + dg) * 2;
        CP16(o + AQHB, sh);
        CP16(o + AQHB + 16, sh + 8);
        CP16(o + AQLB, sl);
        CP16(o + AQLB + 16, sl + 8);
    }
    CP_COMMIT();
    CP_WAIT0();
    __syncthreads();

    const int mt  = w & 1;
    const int nb  = (w >> 1) * 16;
    const int ds  = w >> 1;
    const int l16 = lane & 15, lh8 = (lane >> 4) * 8;

    uint32_t qh[4][4], ql[4][4];
#pragma unroll
    for (int ks = 0; ks < 4; ks++) {
        uint32_t ad = sb + AQHB + (uint32_t)((mt * 16 + l16) * KSTH + ks * 16 + lh8) * 2;
        LDSM4(qh[ks], ad);
        LDSM4(ql[ks], ad + (AQLB - AQHB));
    }

    float rs0 = 0.f, rs1 = 0.f;
    const int r0 = mt * 16 + (lane >> 2), r1 = r0 + 8;

    // ======================= QK phase ======================================
    for (int cc = 0; cc < 9; cc++) {
        const int cb = cc * 64;
        const int W  = (cc == 8) ? 32 : 64;
        __syncthreads();
        // stage K chunk (pre-split) via cp.async; zero-fill OOB keys
        {
            int row = t >> 2, dg = (t & 3) * 16;
            if (row < W) {
                int key = kmin + cb + row;
                bool ok = (key >= 0 && key < S_LEN);
                int keyc = ok ? key : 0;
                int sz = ok ? 16 : 0;
                const __nv_bfloat16* sh = g_kh + (size_t)keyc * HID + hoff + dg;
                const __nv_bfloat16* sl = g_kl + (size_t)keyc * HID + hoff + dg;
                uint32_t o = sb + AKVB + (uint32_t)(row * KSTH + dg) * 2;
                CP16Z(o, sh, sz);
                CP16Z(o + 16, sh + 8, sz);
                CP16Z(o + 9216, sl, sz);
                CP16Z(o + 9216 + 16, sl + 8, sz);
            }
        }
        CP_COMMIT();
        CP_WAIT0();
        __syncthreads();

        if (nb < W) {
            float acc[2][4];
#pragma unroll
            for (int j = 0; j < 2; j++)
#pragma unroll
                for (int e = 0; e < 4; e++) acc[j][e] = 0.f;

#pragma unroll
            for (int ks = 0; ks < 4; ks++) {
                uint32_t bh[4], bl[4];
                uint32_t bd = sb + AKVB +
                    (uint32_t)((nb + l16) * KSTH + ks * 16 + lh8) * 2;
                LDSM4(bh, bd);
                LDSM4(bl, bd + 9216);
#pragma unroll
                for (int j = 0; j < 2; j++) {
                    MMA16816(acc[j], qh[ks], bh[j], bh[j + 2]);
                    MMA16816(acc[j], qh[ks], bl[j], bl[j + 2]);
                    MMA16816(acc[j], ql[ks], bh[j], bh[j + 2]);
                }
            }
#pragma unroll
            for (int j = 0; j < 2; j++) {
                int c0 = cb + nb + j * 8 + (lane & 3) * 2;
                float o00 = ((unsigned)(c0 - r0) < WIN)
                            ? __expf(acc[j][0] * 0.125f) : 0.f;
                float o01 = ((unsigned)(c0 + 1 - r0) < WIN)
                            ? __expf(acc[j][1] * 0.125f) : 0.f;
                float o10 = ((unsigned)(c0 - r1) < WIN)
                            ? __expf(acc[j][2] * 0.125f) : 0.f;
                float o11 = ((unsigned)(c0 + 1 - r1) < WIN)
                            ? __expf(acc[j][3] * 0.125f) : 0.f;
                rs0 += o00 + o01;
                rs1 += o10 + o11;
                uint32_t hp, lp;
                sp2(o00, o01, hp, lp);
                *(uint32_t*)(am + APHB + (uint32_t)(r0 * PSTH + c0) * 2) = hp;
                *(uint32_t*)(am + APLB + (uint32_t)(r0 * PSTH + c0) * 2) = lp;
                sp2(o10, o11, hp, lp);
                *(uint32_t*)(am + APHB + (uint32_t)(r1 * PSTH + c0) * 2) = hp;
                *(uint32_t*)(am + APLB + (uint32_t)(r1 * PSTH + c0) * 2) = lp;
            }
        }
    }

    // ---- deterministic row sums ----
    rs0 += __shfl_xor_sync(0xFFFFFFFFu, rs0, 1);
    rs0 += __shfl_xor_sync(0xFFFFFFFFu, rs0, 2);
    rs1 += __shfl_xor_sync(0xFFFFFFFFu, rs1, 1);
    rs1 += __shfl_xor_sync(0xFFFFFFFFu, rs1, 2);
    if ((lane & 3) == 0) {
        part[w * 32 + r0] = rs0;
        part[w * 32 + r1] = rs1;
    }
    __syncthreads();
    if (t < 32) {
        float s = 0.f;
#pragma unroll
        for (int w8 = 0; w8 < 8; w8++) s += part[w8 * 32 + t];
        sinv[t] = 1.f / s;
    }
    __syncthreads();

    if (write_probs) {
        float* pr = probs + ((size_t)h * S_LEN + q0) * WIN;
        for (int idx = t; idx < QT * WIN; idx += 256) {
            int qi = idx >> 9, ww = idx & (WIN - 1);
            uint32_t o = (uint32_t)(qi * PSTH + qi + ww) * 2;
            float ph = __bfloat162float(*(__nv_bfloat16*)(am + APHB + o));
            float pl = __bfloat162float(*(__nv_bfloat16*)(am + APLB + o));
            pr[(size_t)qi * WIN + ww] = (ph + pl) * sinv[qi];
        }
    }

    // ======================= PV phase ======================================
    float acc2[2][4];
#pragma unroll
    for (int j = 0; j < 2; j++)
#pragma unroll
        for (int e = 0; e < 4; e++) acc2[j][e] = 0.f;

    for (int cc = 0; cc < 9; cc++) {
        const int cb = cc * 64;
        const int W  = (cc == 8) ? 32 : 64;
        __syncthreads();
        // stage V transposed [d][key] from pre-split buffers
        {
            int keyl = t >> 2, dg = (t & 3) * 16;
            if (keyl < W) {
                int key = kmin + cb + keyl;
                bool ok = (key >= 0 && key < S_LEN);
                uint4 hv[2] = {{0,0,0,0},{0,0,0,0}};
                uint4 lv[2] = {{0,0,0,0},{0,0,0,0}};
                if (ok) {
                    const uint4* sh =
                        (const uint4*)(g_vh + (size_t)key * HID + hoff + dg);
                    const uint4* sl =
                        (const uint4*)(g_vl + (size_t)key * HID + hoff + dg);
                    hv[0] = sh[0]; hv[1] = sh[1];
                    lv[0] = sl[0]; lv[1] = sl[1];
                }
                const unsigned short* hs = (const unsigned short*)hv;
                const unsigned short* ls = (const unsigned short*)lv;
#pragma unroll
                for (int u = 0; u < 16; u++) {
                    uint32_t o = (uint32_t)((dg + u) * KSTH + keyl) * 2;
                    *(unsigned short*)(am + AKVB + o)        = hs[u];
                    *(unsigned short*)(am + AKVB + 9216 + o) = ls[u];
                }
            }
        }
        __syncthreads();

        const int nks = W >> 4;
        for (int ks = 0; ks < nks; ks++) {
            uint32_t pah[4], pal[4], vbh[4], vbl[4];
            uint32_t pd = sb + APHB +
                (uint32_t)((mt * 16 + l16) * PSTH + cb + ks * 16 + lh8) * 2;
            LDSM4(pah, pd);
            LDSM4(pal, pd + (APLB - APHB));
            uint32_t vd = sb + AKVB +
                (uint32_t)((ds * 16 + l16) * KSTH + ks * 16 + lh8) * 2;
            LDSM4(vbh, vd);
            LDSM4(vbl, vd + 9216);
#pragma unroll
            for (int j = 0; j < 2; j++) {
                MMA16816(acc2[j], pah, vbh[j], vbh[j + 2]);
                MMA16816(acc2[j], pah, vbl[j], vbl[j + 2]);
                MMA16816(acc2[j], pal, vbh[j], vbh[j + 2]);
            }
        }
    }

    // ---- ctx epilogue: write split bf16 directly into hgemm_o's A buffers ----
    {
        float i0 = sinv[r0], i1 = sinv[r1];
#pragma unroll
        for (int j = 0; j < 2; j++) {
            int c = ds * 16 + j * 8 + (lane & 3) * 2;
            uint32_t hp, lp;
            sp2(acc2[j][0] * i0, acc2[j][1] * i0, hp, lp);
            *(uint32_t*)&g_xh[(size_t)(q0 + r0) * HID + hoff + c] = hp;
            *(uint32_t*)&g_xl[(size_t)(q0 + r0) * HID + hoff + c] = lp;
            sp2(acc2[j][2] * i1, acc2[j][3] * i1, hp, lp);
            *(uint32_t*)&g_xh[(size_t)(q0 + r1) * HID + hoff + c] = hp;
            *(uint32_t*)&g_xl[(size_t)(q0 + r1) * HID + hoff + c] = lp;
        }
    }
}

// ============================================================================
extern "C" void kernel_launch(void* const* d_in, const int* in_sizes, int n_in,
                              void* d_out, int out_size)
{
    const float* X  = (const float*)d_in[0];
    const float* Wq = (const float*)d_in[1];
    const float* bq = (const float*)d_in[2];
    const float* Wk = (const float*)d_in[3];
    const float* bk = (const float*)d_in[4];
    const float* Wv = (const float*)d_in[5];
    const float* bv = (const float*)d_in[6];
    const float* Wo = (const float*)d_in[7];
    const float* bo = (const float*)d_in[8];

    float* out = (float*)d_out;
    const size_t OUT_ELEMS   = (size_t)S_LEN * HID;
    const size_t PROBS_ELEMS = (size_t)NH * S_LEN * WIN;
    float* probs = out + OUT_ELEMS;
    int write_probs = ((size_t)out_size >= OUT_ELEMS + PROBS_ELEMS) ? 1 : 0;

    cudaFuncSetAttribute(attn_kernel,
                         cudaFuncAttributeMaxDynamicSharedMemorySize, ASMEM);
    cudaFuncSetAttribute(hgemm_qkv,
                         cudaFuncAttributeMaxDynamicSharedMemorySize, GSMEM);
    cudaFuncSetAttribute(hgemm_o,
                         cudaFuncAttributeMaxDynamicSharedMemorySize, GSMEM);

    conv_act<<<(S_LEN * HID) / 1024, 256>>>(X);
    dim3 ct(32, 8), cg(HID / 32, HID / 32);
    conv_w_t<<<cg, ct>>>(Wq, 0);
    conv_w_t<<<cg, ct>>>(Wk, HID * HID);
    conv_w_t<<<cg, ct>>>(Wv, 2 * HID * HID);
    conv_w_t<<<cg, ct>>>(Wo, 3 * HID * HID);

    hgemm_qkv<<<dim3(24, 16), 256, GSMEM>>>(bq, bk, bv);

    dim3 agrid(S_LEN / QT, NH);
    attn_kernel<<<agrid, 256, ASMEM>>>(probs, write_probs);

    hgemm_o<<<dim3(8, 16), 256, GSMEM>>>(bo, out);
}